// round 1
// baseline (speedup 1.0000x reference)
#include <cuda_runtime.h>
#include <math.h>

#define NN 50000
#define EE 100000
#define HH 512
#define TT 6
#define SORT_CAP (EE + TT * 64)   /* 100384: padded type-sorted edge list */

/* ---------------- scratch (static device globals; no allocation) ---------- */
__device__ float g_proposed[(size_t)NN * HH];   /* ~102 MB */
__device__ int   g_sorted[SORT_CAP];
__device__ int   g_tcount[TT];
__device__ int   g_tcur[TT];
__device__ int   g_toff[TT + 1];

__device__ __forceinline__ float sigmoidf_(float x) {
    return 1.0f / (1.0f + expf(-x));
}

/* ---------------- init ---------------------------------------------------- */
__global__ void k_init_proposed() {
    size_t i = (size_t)blockIdx.x * blockDim.x + threadIdx.x;
    size_t n4 = (size_t)NN * HH / 4;
    if (i < n4) ((float4*)g_proposed)[i] = make_float4(0.f, 0.f, 0.f, 0.f);
}

__global__ void k_init_meta() {
    int i = blockIdx.x * blockDim.x + threadIdx.x;
    if (i < TT) { g_tcount[i] = 0; g_tcur[i] = 0; }
    if (i < SORT_CAP) g_sorted[i] = -1;
}

/* ---------------- type-grouping (counting sort, 64-aligned groups) -------- */
__global__ void k_hist(const int* __restrict__ et) {
    int e = blockIdx.x * blockDim.x + threadIdx.x;
    if (e < EE) atomicAdd(&g_tcount[et[e]], 1);
}

__global__ void k_offsets() {
    if (threadIdx.x == 0 && blockIdx.x == 0) {
        int off = 0;
        for (int t = 0; t < TT; t++) {
            g_toff[t] = off;
            off += ((g_tcount[t] + 63) >> 6) << 6;   /* pad to 64 */
        }
        g_toff[TT] = off;
    }
}

__global__ void k_scatter(const int* __restrict__ et) {
    int e = blockIdx.x * blockDim.x + threadIdx.x;
    if (e < EE) {
        int t = et[e];
        int pos = g_toff[t] + atomicAdd(&g_tcur[t], 1);
        g_sorted[pos] = e;
    }
}

/* ---------------- edge message GEMM + scatter-add -------------------------
 * Tile: 64 edges x 64 cols, K = 512 in chunks of 16. 256 threads, 4x4 micro.
 * A = gather(emb, src)  [64 x 512]
 * B = W_edge[:, t*512 + j0 : +64]   (row-major, row stride T*H = 3072)
 * C += b_edge slice, then atomicAdd into g_proposed[dest] rows.
 * ------------------------------------------------------------------------- */
__global__ __launch_bounds__(256) void k_edge_gemm(
    const float* __restrict__ emb, const int* __restrict__ src,
    const int* __restrict__ dst, const float* __restrict__ W_edge,
    const float* __restrict__ b_edge)
{
    int start = blockIdx.x * 64;
    if (start >= g_toff[TT]) return;

    int t = 0;
#pragma unroll
    for (int i = 1; i < TT; i++) if (start >= g_toff[i]) t = i;
    int j0 = blockIdx.y * 64;

    __shared__ float As[16][64];
    __shared__ float Bs[16][64];
    __shared__ int s_eid[64];
    __shared__ int s_dst[64];
    __shared__ int s_srow[64];

    int tid = threadIdx.x;
    if (tid < 64) {
        int e = g_sorted[start + tid];
        s_eid[tid]  = e;
        s_srow[tid] = (e >= 0) ? src[e] : -1;
        s_dst[tid]  = (e >= 0) ? dst[e] : 0;
    }
    __syncthreads();

    int m_load = tid >> 2;          /* 0..63 : A row     */
    int c_load = tid & 3;           /* 0..3  : A k-quad  */
    int bk = tid >> 4;              /* 0..15 : B k-row   */
    int bj = (tid & 15) << 2;       /* 0..60 : B col quad*/
    int ty = tid >> 4, tx = tid & 15;

    int arow = s_srow[m_load];
    bool avalid = (arow >= 0);
    const float* aptr = emb + (size_t)(avalid ? arow : 0) * HH;
    const float* bptr = W_edge + (size_t)t * HH + j0 + bj;

    float acc[4][4];
#pragma unroll
    for (int i = 0; i < 4; i++)
#pragma unroll
        for (int j = 0; j < 4; j++) acc[i][j] = 0.f;

    for (int k0 = 0; k0 < HH; k0 += 16) {
        float4 av = make_float4(0.f, 0.f, 0.f, 0.f);
        if (avalid) av = *(const float4*)(aptr + k0 + (c_load << 2));
        float4 bv = *(const float4*)(bptr + (size_t)(k0 + bk) * (TT * HH));
        __syncthreads();
        As[(c_load << 2) + 0][m_load] = av.x;
        As[(c_load << 2) + 1][m_load] = av.y;
        As[(c_load << 2) + 2][m_load] = av.z;
        As[(c_load << 2) + 3][m_load] = av.w;
        *(float4*)&Bs[bk][bj] = bv;
        __syncthreads();
#pragma unroll
        for (int kk = 0; kk < 16; kk++) {
            float4 a4 = *(const float4*)&As[kk][ty << 2];
            float4 b4 = *(const float4*)&Bs[kk][tx << 2];
            float a[4] = {a4.x, a4.y, a4.z, a4.w};
            float b[4] = {b4.x, b4.y, b4.z, b4.w};
#pragma unroll
            for (int i = 0; i < 4; i++)
#pragma unroll
                for (int j = 0; j < 4; j++)
                    acc[i][j] = fmaf(a[i], b[j], acc[i][j]);
        }
    }

    float bias[4];
#pragma unroll
    for (int j = 0; j < 4; j++) bias[j] = b_edge[t * HH + j0 + (tx << 2) + j];

#pragma unroll
    for (int i = 0; i < 4; i++) {
        int e = s_eid[(ty << 2) + i];
        if (e < 0) continue;
        float* outp = g_proposed + (size_t)s_dst[(ty << 2) + i] * HH + j0 + (tx << 2);
#pragma unroll
        for (int j = 0; j < 4; j++)
            atomicAdd(outp + j, acc[i][j] + bias[j]);
    }
}

/* ---------------- fused GRU kernel ----------------------------------------
 * For a 64-node x 64-col tile, one K sweep computes 4 accumulator sets:
 *   rr = p@W_ir + h@W_hr, zz = p@W_iz + h@W_hz, np = p@W_in, nh = h@W_hn
 * then applies the gates. 256 threads, 4x4 micro, 6 weight tiles in smem.
 * ------------------------------------------------------------------------- */
__global__ __launch_bounds__(256, 2) void k_gru(
    const float* __restrict__ emb,
    const float* __restrict__ Wir, const float* __restrict__ Wiz,
    const float* __restrict__ Win,
    const float* __restrict__ bir, const float* __restrict__ biz,
    const float* __restrict__ bin,
    const float* __restrict__ Whr, const float* __restrict__ Whz,
    const float* __restrict__ Whn,
    const float* __restrict__ bhn,
    float* __restrict__ out)
{
    int m0 = blockIdx.x * 64;
    int j0 = blockIdx.y * 64;

    __shared__ float Ap[16][64], Ah[16][64];
    __shared__ float Bir_s[16][64], Biz_s[16][64], Bin_s[16][64];
    __shared__ float Bhr_s[16][64], Bhz_s[16][64], Bhn_s[16][64];

    int tid = threadIdx.x;
    int m_load = tid >> 2, c_load = tid & 3;
    int bk = tid >> 4, bj = (tid & 15) << 2;
    int ty = tid >> 4, tx = tid & 15;

    int row = m0 + m_load;
    bool rvalid = (row < NN);
    const float* prow = g_proposed + (size_t)(rvalid ? row : 0) * HH;
    const float* hrow = emb + (size_t)(rvalid ? row : 0) * HH;

    float rr[4][4], zz[4][4], np[4][4], nh[4][4];
#pragma unroll
    for (int i = 0; i < 4; i++)
#pragma unroll
        for (int j = 0; j < 4; j++) {
            rr[i][j] = 0.f; zz[i][j] = 0.f; np[i][j] = 0.f; nh[i][j] = 0.f;
        }

    for (int k0 = 0; k0 < HH; k0 += 16) {
        float4 ap = make_float4(0.f, 0.f, 0.f, 0.f);
        float4 ah = make_float4(0.f, 0.f, 0.f, 0.f);
        if (rvalid) {
            ap = *(const float4*)(prow + k0 + (c_load << 2));
            ah = *(const float4*)(hrow + k0 + (c_load << 2));
        }
        size_t wofs = (size_t)(k0 + bk) * HH + j0 + bj;
        float4 vir = *(const float4*)(Wir + wofs);
        float4 viz = *(const float4*)(Wiz + wofs);
        float4 vin = *(const float4*)(Win + wofs);
        float4 vhr = *(const float4*)(Whr + wofs);
        float4 vhz = *(const float4*)(Whz + wofs);
        float4 vhn = *(const float4*)(Whn + wofs);
        __syncthreads();
        Ap[(c_load << 2) + 0][m_load] = ap.x;
        Ap[(c_load << 2) + 1][m_load] = ap.y;
        Ap[(c_load << 2) + 2][m_load] = ap.z;
        Ap[(c_load << 2) + 3][m_load] = ap.w;
        Ah[(c_load << 2) + 0][m_load] = ah.x;
        Ah[(c_load << 2) + 1][m_load] = ah.y;
        Ah[(c_load << 2) + 2][m_load] = ah.z;
        Ah[(c_load << 2) + 3][m_load] = ah.w;
        *(float4*)&Bir_s[bk][bj] = vir;
        *(float4*)&Biz_s[bk][bj] = viz;
        *(float4*)&Bin_s[bk][bj] = vin;
        *(float4*)&Bhr_s[bk][bj] = vhr;
        *(float4*)&Bhz_s[bk][bj] = vhz;
        *(float4*)&Bhn_s[bk][bj] = vhn;
        __syncthreads();
#pragma unroll
        for (int kk = 0; kk < 16; kk++) {
            float4 a4 = *(const float4*)&Ap[kk][ty << 2];
            float4 h4 = *(const float4*)&Ah[kk][ty << 2];
            float ap_[4] = {a4.x, a4.y, a4.z, a4.w};
            float ah_[4] = {h4.x, h4.y, h4.z, h4.w};
            float4 b4; float b[4];

            b4 = *(const float4*)&Bir_s[kk][tx << 2];
            b[0]=b4.x; b[1]=b4.y; b[2]=b4.z; b[3]=b4.w;
#pragma unroll
            for (int i = 0; i < 4; i++)
#pragma unroll
                for (int j = 0; j < 4; j++) rr[i][j] = fmaf(ap_[i], b[j], rr[i][j]);

            b4 = *(const float4*)&Bhr_s[kk][tx << 2];
            b[0]=b4.x; b[1]=b4.y; b[2]=b4.z; b[3]=b4.w;
#pragma unroll
            for (int i = 0; i < 4; i++)
#pragma unroll
                for (int j = 0; j < 4; j++) rr[i][j] = fmaf(ah_[i], b[j], rr[i][j]);

            b4 = *(const float4*)&Biz_s[kk][tx << 2];
            b[0]=b4.x; b[1]=b4.y; b[2]=b4.z; b[3]=b4.w;
#pragma unroll
            for (int i = 0; i < 4; i++)
#pragma unroll
                for (int j = 0; j < 4; j++) zz[i][j] = fmaf(ap_[i], b[j], zz[i][j]);

            b4 = *(const float4*)&Bhz_s[kk][tx << 2];
            b[0]=b4.x; b[1]=b4.y; b[2]=b4.z; b[3]=b4.w;
#pragma unroll
            for (int i = 0; i < 4; i++)
#pragma unroll
                for (int j = 0; j < 4; j++) zz[i][j] = fmaf(ah_[i], b[j], zz[i][j]);

            b4 = *(const float4*)&Bin_s[kk][tx << 2];
            b[0]=b4.x; b[1]=b4.y; b[2]=b4.z; b[3]=b4.w;
#pragma unroll
            for (int i = 0; i < 4; i++)
#pragma unroll
                for (int j = 0; j < 4; j++) np[i][j] = fmaf(ap_[i], b[j], np[i][j]);

            b4 = *(const float4*)&Bhn_s[kk][tx << 2];
            b[0]=b4.x; b[1]=b4.y; b[2]=b4.z; b[3]=b4.w;
#pragma unroll
            for (int i = 0; i < 4; i++)
#pragma unroll
                for (int j = 0; j < 4; j++) nh[i][j] = fmaf(ah_[i], b[j], nh[i][j]);
        }
    }

    /* epilogue: gate math */
#pragma unroll
    for (int i = 0; i < 4; i++) {
        int node = m0 + (ty << 2) + i;
        if (node >= NN) continue;
#pragma unroll
        for (int j = 0; j < 4; j++) {
            int col = j0 + (tx << 2) + j;
            float h = emb[(size_t)node * HH + col];
            float r = sigmoidf_(rr[i][j] + bir[col]);
            float z = sigmoidf_(zz[i][j] + biz[col]);
            float n = tanhf(np[i][j] + bin[col] + r * (nh[i][j] + bhn[col]));
            out[(size_t)node * HH + col] = (1.0f - z) * n + z * h;
        }
    }
}

/* ---------------- launch --------------------------------------------------- */
extern "C" void kernel_launch(void* const* d_in, const int* in_sizes, int n_in,
                              void* d_out, int out_size)
{
    /* scalars (num_nodes, hidden_size) may or may not appear as inputs */
    int s = (n_in >= 18) ? 2 : 0;

    const float* emb    = (const float*)d_in[0];
    const int*   src    = (const int*)d_in[1];
    const int*   dst    = (const int*)d_in[2];
    const int*   et     = (const int*)d_in[3];
    const float* W_edge = (const float*)d_in[4 + s];
    const float* b_edge = (const float*)d_in[5 + s];
    const float* Wir    = (const float*)d_in[6 + s];
    const float* Wiz    = (const float*)d_in[7 + s];
    const float* Win    = (const float*)d_in[8 + s];
    const float* bir    = (const float*)d_in[9 + s];
    const float* biz    = (const float*)d_in[10 + s];
    const float* bin    = (const float*)d_in[11 + s];
    const float* Whr    = (const float*)d_in[12 + s];
    const float* Whz    = (const float*)d_in[13 + s];
    const float* Whn    = (const float*)d_in[14 + s];
    const float* bhn    = (const float*)d_in[15 + s];
    float* out = (float*)d_out;

    k_init_proposed<<<(NN * HH / 4 + 255) / 256, 256>>>();
    k_init_meta<<<(SORT_CAP + 255) / 256, 256>>>();
    k_hist<<<(EE + 255) / 256, 256>>>(et);
    k_offsets<<<1, 32>>>();
    k_scatter<<<(EE + 255) / 256, 256>>>(et);

    dim3 eg((EE + TT * 64 + 63) / 64, HH / 64);
    k_edge_gemm<<<eg, 256>>>(emb, src, dst, W_edge, b_edge);

    dim3 gg((NN + 63) / 64, HH / 64);
    k_gru<<<gg, 256>>>(emb, Wir, Wiz, Win, bir, biz, bin,
                       Whr, Whz, Whn, bhn, out);
}

// round 2
// speedup vs baseline: 1.7413x; 1.7413x over previous
#include <cuda_runtime.h>
#include <math.h>

#define NN 50000
#define EE 100000
#define HH 512
#define TT 6
#define MPAD 50048                     /* NN padded to 128 */
#define SORT_CAP (EE + TT * 128)       /* padded type-sorted edge list */

/* ---------------- scratch (static device globals; no allocation) ---------- */
__device__ float g_proposed[(size_t)NN * HH];
__device__ float g_rr[(size_t)NN * HH];
__device__ float g_zz[(size_t)NN * HH];
__device__ float g_np[(size_t)NN * HH];
__device__ float g_nh[(size_t)NN * HH];
__device__ int   g_sorted[SORT_CAP];
__device__ int   g_tcount[TT];
__device__ int   g_tcur[TT];
__device__ int   g_toff[TT + 1];

/* ---------------- helpers -------------------------------------------------- */
__device__ __forceinline__ unsigned f2t(float f) {
    unsigned u;
    asm("cvt.rna.tf32.f32 %0, %1;" : "=r"(u) : "f"(f));
    return u;
}

__device__ __forceinline__ void mma8(float c[4], const unsigned a[4], const unsigned b[2]) {
    asm volatile(
        "mma.sync.aligned.m16n8k8.row.col.f32.tf32.tf32.f32 "
        "{%0,%1,%2,%3},{%4,%5,%6,%7},{%8,%9},{%0,%1,%2,%3};"
        : "+f"(c[0]), "+f"(c[1]), "+f"(c[2]), "+f"(c[3])
        : "r"(a[0]), "r"(a[1]), "r"(a[2]), "r"(a[3]), "r"(b[0]), "r"(b[1]));
}

__device__ __forceinline__ float sigmoidf_(float x) {
    return 1.0f / (1.0f + expf(-x));
}

/* A smem: [128][20] u32 (stride 20 -> conflict-free frag loads)
 * B smem: [16][72]  u32 (stride 72 -> conflict-free frag loads)          */
#define ASTR 20
#define BSTR 72
#define KC 16

/* ---------------- init ---------------------------------------------------- */
__global__ void k_init_proposed() {
    size_t i = (size_t)blockIdx.x * blockDim.x + threadIdx.x;
    size_t n4 = (size_t)NN * HH / 4;
    if (i < n4) ((float4*)g_proposed)[i] = make_float4(0.f, 0.f, 0.f, 0.f);
}

__global__ void k_init_meta() {
    int i = blockIdx.x * blockDim.x + threadIdx.x;
    if (i < TT) { g_tcount[i] = 0; g_tcur[i] = 0; }
    if (i < SORT_CAP) g_sorted[i] = -1;
}

__global__ void k_hist(const int* __restrict__ et) {
    int e = blockIdx.x * blockDim.x + threadIdx.x;
    if (e < EE) atomicAdd(&g_tcount[et[e]], 1);
}

__global__ void k_offsets() {
    if (threadIdx.x == 0 && blockIdx.x == 0) {
        int off = 0;
        for (int t = 0; t < TT; t++) {
            g_toff[t] = off;
            off += ((g_tcount[t] + 127) >> 7) << 7;   /* pad to 128 */
        }
        g_toff[TT] = off;
    }
}

__global__ void k_scatter(const int* __restrict__ et) {
    int e = blockIdx.x * blockDim.x + threadIdx.x;
    if (e < EE) {
        int t = et[e];
        int pos = g_toff[t] + atomicAdd(&g_tcur[t], 1);
        g_sorted[pos] = e;
    }
}

/* ---------------- fragment compute: 8 warps, warp tile 32x32 --------------- */
/* per chunk of KC=16: two k-steps of 8 */
__device__ __forceinline__ void compute_chunk(
    const unsigned* __restrict__ As, const unsigned* __restrict__ Bs,
    int wm, int wn, int gid, int tig, float acc[2][4][4])
{
#pragma unroll
    for (int ks = 0; ks < KC; ks += 8) {
        unsigned a[2][4];
#pragma unroll
        for (int mi = 0; mi < 2; mi++) {
            int r0 = wm + mi * 16 + gid;
            a[mi][0] = As[(r0)     * ASTR + ks + tig];
            a[mi][1] = As[(r0 + 8) * ASTR + ks + tig];
            a[mi][2] = As[(r0)     * ASTR + ks + tig + 4];
            a[mi][3] = As[(r0 + 8) * ASTR + ks + tig + 4];
        }
        unsigned b[4][2];
#pragma unroll
        for (int ni = 0; ni < 4; ni++) {
            int c0 = wn + ni * 8 + gid;
            b[ni][0] = Bs[(ks + tig)     * BSTR + c0];
            b[ni][1] = Bs[(ks + tig + 4) * BSTR + c0];
        }
#pragma unroll
        for (int mi = 0; mi < 2; mi++)
#pragma unroll
            for (int ni = 0; ni < 4; ni++)
                mma8(acc[mi][ni], a[mi], b[ni]);
    }
}

/* loaders: A chunk [128][KC] floats: 512 float4, 2/thread.
 * W chunk [KC][64] floats: 256 float4, 1/thread. */
__device__ __forceinline__ void stA(unsigned* As, int tid, const float4 v[2]) {
#pragma unroll
    for (int i = 0; i < 2; i++) {
        int idx = tid * 2 + i, row = idx >> 2, q = idx & 3;
        unsigned* p = As + row * ASTR + q * 4;
        p[0] = f2t(v[i].x); p[1] = f2t(v[i].y); p[2] = f2t(v[i].z); p[3] = f2t(v[i].w);
    }
}
__device__ __forceinline__ void stB(unsigned* Bs, int tid, float4 v) {
    int row = tid >> 4, q = tid & 15;
    unsigned* p = Bs + row * BSTR + q * 4;
    p[0] = f2t(v.x); p[1] = f2t(v.y); p[2] = f2t(v.z); p[3] = f2t(v.w);
}
__device__ __forceinline__ void ldA(float4 v[2], const float* __restrict__ A,
                                    int m0, int tid, int k0) {
#pragma unroll
    for (int i = 0; i < 2; i++) {
        int idx = tid * 2 + i, row = idx >> 2, q = idx & 3;
        int r = m0 + row; if (r >= NN) r = NN - 1;
        v[i] = *(const float4*)(A + (size_t)r * HH + k0 + q * 4);
    }
}
__device__ __forceinline__ float4 ldB(const float* __restrict__ W, size_t ldw,
                                      int j0, int tid, int k0) {
    int row = tid >> 4, q = tid & 15;
    return *(const float4*)(W + (size_t)(k0 + row) * ldw + j0 + q * 4);
}

/* ---------------- GEMM: C = A1@W1 + A2@W2 (dual) --------------------------- */
__global__ __launch_bounds__(256, 2) void k_gemm2(
    const float* __restrict__ A1, const float* __restrict__ W1,
    const float* __restrict__ A2, const float* __restrict__ W2,
    float* __restrict__ C)
{
    __shared__ unsigned As1[128 * ASTR], As2[128 * ASTR];
    __shared__ unsigned Bs1[KC * BSTR], Bs2[KC * BSTR];

    int tid = threadIdx.x, lane = tid & 31, warp = tid >> 5;
    int gid = lane >> 2, tig = lane & 3;
    int wm = (warp >> 1) * 32, wn = (warp & 1) * 32;
    int m0 = blockIdx.x * 128, j0 = blockIdx.y * 64;

    float acc[2][4][4];
#pragma unroll
    for (int mi = 0; mi < 2; mi++)
#pragma unroll
        for (int ni = 0; ni < 4; ni++)
#pragma unroll
            for (int q = 0; q < 4; q++) acc[mi][ni][q] = 0.f;

    float4 pa1[2], pa2[2], pw1, pw2;
    ldA(pa1, A1, m0, tid, 0); ldA(pa2, A2, m0, tid, 0);
    pw1 = ldB(W1, HH, j0, tid, 0); pw2 = ldB(W2, HH, j0, tid, 0);

    for (int c = 0; c < HH / KC; c++) {
        stA(As1, tid, pa1); stA(As2, tid, pa2);
        stB(Bs1, tid, pw1); stB(Bs2, tid, pw2);
        __syncthreads();
        if (c + 1 < HH / KC) {
            int k0 = (c + 1) * KC;
            ldA(pa1, A1, m0, tid, k0); ldA(pa2, A2, m0, tid, k0);
            pw1 = ldB(W1, HH, j0, tid, k0); pw2 = ldB(W2, HH, j0, tid, k0);
        }
        compute_chunk(As1, Bs1, wm, wn, gid, tig, acc);
        compute_chunk(As2, Bs2, wm, wn, gid, tig, acc);
        __syncthreads();
    }

#pragma unroll
    for (int mi = 0; mi < 2; mi++) {
#pragma unroll
        for (int ni = 0; ni < 4; ni++) {
            int col = j0 + wn + ni * 8 + tig * 2;
            int r0 = m0 + wm + mi * 16 + gid;
            if (r0 < NN)
                *(float2*)(C + (size_t)r0 * HH + col) = make_float2(acc[mi][ni][0], acc[mi][ni][1]);
            if (r0 + 8 < NN)
                *(float2*)(C + (size_t)(r0 + 8) * HH + col) = make_float2(acc[mi][ni][2], acc[mi][ni][3]);
        }
    }
}

/* ---------------- GEMM: C = A@W (single) ----------------------------------- */
__global__ __launch_bounds__(256, 2) void k_gemm1(
    const float* __restrict__ A, const float* __restrict__ W,
    float* __restrict__ C)
{
    __shared__ unsigned As[128 * ASTR];
    __shared__ unsigned Bs[KC * BSTR];

    int tid = threadIdx.x, lane = tid & 31, warp = tid >> 5;
    int gid = lane >> 2, tig = lane & 3;
    int wm = (warp >> 1) * 32, wn = (warp & 1) * 32;
    int m0 = blockIdx.x * 128, j0 = blockIdx.y * 64;

    float acc[2][4][4];
#pragma unroll
    for (int mi = 0; mi < 2; mi++)
#pragma unroll
        for (int ni = 0; ni < 4; ni++)
#pragma unroll
            for (int q = 0; q < 4; q++) acc[mi][ni][q] = 0.f;

    float4 pa[2]; float4 pw;
    ldA(pa, A, m0, tid, 0); pw = ldB(W, HH, j0, tid, 0);

    for (int c = 0; c < HH / KC; c++) {
        stA(As, tid, pa); stB(Bs, tid, pw);
        __syncthreads();
        if (c + 1 < HH / KC) {
            int k0 = (c + 1) * KC;
            ldA(pa, A, m0, tid, k0); pw = ldB(W, HH, j0, tid, k0);
        }
        compute_chunk(As, Bs, wm, wn, gid, tig, acc);
        __syncthreads();
    }

#pragma unroll
    for (int mi = 0; mi < 2; mi++) {
#pragma unroll
        for (int ni = 0; ni < 4; ni++) {
            int col = j0 + wn + ni * 8 + tig * 2;
            int r0 = m0 + wm + mi * 16 + gid;
            if (r0 < NN)
                *(float2*)(C + (size_t)r0 * HH + col) = make_float2(acc[mi][ni][0], acc[mi][ni][1]);
            if (r0 + 8 < NN)
                *(float2*)(C + (size_t)(r0 + 8) * HH + col) = make_float2(acc[mi][ni][2], acc[mi][ni][3]);
        }
    }
}

/* ---------------- edge GEMM: gather + bias + atomic scatter ---------------- */
__global__ __launch_bounds__(256, 2) void k_edge_gemm(
    const float* __restrict__ emb, const int* __restrict__ src,
    const int* __restrict__ dst, const float* __restrict__ W_edge,
    const float* __restrict__ b_edge)
{
    int start = blockIdx.x * 128;
    if (start >= g_toff[TT]) return;
    int t = 0;
#pragma unroll
    for (int i = 1; i < TT; i++) if (start >= g_toff[i]) t = i;

    __shared__ unsigned As[128 * ASTR];
    __shared__ unsigned Bs[KC * BSTR];
    __shared__ int s_srow[128];
    __shared__ int s_dst[128];

    int tid = threadIdx.x, lane = tid & 31, warp = tid >> 5;
    int gid = lane >> 2, tig = lane & 3;
    int wm = (warp >> 1) * 32, wn = (warp & 1) * 32;
    int j0 = blockIdx.y * 64;

    if (tid < 128) {
        int e = g_sorted[start + tid];
        s_srow[tid] = (e >= 0) ? src[e] : -1;
        s_dst[tid]  = (e >= 0) ? dst[e] : -1;
    }
    __syncthreads();

    float acc[2][4][4];
#pragma unroll
    for (int mi = 0; mi < 2; mi++)
#pragma unroll
        for (int ni = 0; ni < 4; ni++)
#pragma unroll
            for (int q = 0; q < 4; q++) acc[mi][ni][q] = 0.f;

    const float* Wt = W_edge + (size_t)t * HH;   /* col offset into [H, T*H] */

    float4 pa[2]; float4 pw;
    {
#pragma unroll
        for (int i = 0; i < 2; i++) {
            int idx = tid * 2 + i, row = idx >> 2, q = idx & 3;
            int nr = s_srow[row];
            pa[i] = (nr >= 0) ? *(const float4*)(emb + (size_t)nr * HH + q * 4)
                              : make_float4(0.f, 0.f, 0.f, 0.f);
        }
        pw = ldB(Wt, (size_t)TT * HH, j0, tid, 0);
    }

    for (int c = 0; c < HH / KC; c++) {
        stA(As, tid, pa); stB(Bs, tid, pw);
        __syncthreads();
        if (c + 1 < HH / KC) {
            int k0 = (c + 1) * KC;
#pragma unroll
            for (int i = 0; i < 2; i++) {
                int idx = tid * 2 + i, row = idx >> 2, q = idx & 3;
                int nr = s_srow[row];
                pa[i] = (nr >= 0) ? *(const float4*)(emb + (size_t)nr * HH + k0 + q * 4)
                                  : make_float4(0.f, 0.f, 0.f, 0.f);
            }
            pw = ldB(Wt, (size_t)TT * HH, j0, tid, k0);
        }
        compute_chunk(As, Bs, wm, wn, gid, tig, acc);
        __syncthreads();
    }

#pragma unroll
    for (int mi = 0; mi < 2; mi++) {
#pragma unroll
        for (int ni = 0; ni < 4; ni++) {
            int col = j0 + wn + ni * 8 + tig * 2;
            float bi0 = b_edge[(size_t)t * HH + col];
            float bi1 = b_edge[(size_t)t * HH + col + 1];
            int ar0 = wm + mi * 16 + gid;
            int d0 = s_dst[ar0];
            if (d0 >= 0) {
                float* p = g_proposed + (size_t)d0 * HH + col;
                atomicAdd(p,     acc[mi][ni][0] + bi0);
                atomicAdd(p + 1, acc[mi][ni][1] + bi1);
            }
            int d1 = s_dst[ar0 + 8];
            if (d1 >= 0) {
                float* p = g_proposed + (size_t)d1 * HH + col;
                atomicAdd(p,     acc[mi][ni][2] + bi0);
                atomicAdd(p + 1, acc[mi][ni][3] + bi1);
            }
        }
    }
}

/* ---------------- elementwise GRU gates ------------------------------------ */
__global__ void k_gates(
    const float* __restrict__ emb,
    const float* __restrict__ bir, const float* __restrict__ biz,
    const float* __restrict__ bin, const float* __restrict__ bhn,
    float* __restrict__ out)
{
    size_t i4 = (size_t)blockIdx.x * blockDim.x + threadIdx.x;
    size_t n4 = (size_t)NN * HH / 4;
    if (i4 >= n4) return;
    int col = (int)(i4 & (HH / 4 - 1)) * 4;

    float4 vr = ((const float4*)g_rr)[i4];
    float4 vz = ((const float4*)g_zz)[i4];
    float4 vp = ((const float4*)g_np)[i4];
    float4 vh = ((const float4*)g_nh)[i4];
    float4 he = ((const float4*)emb)[i4];
    float4 v_bir = *(const float4*)(bir + col);
    float4 v_biz = *(const float4*)(biz + col);
    float4 v_bin = *(const float4*)(bin + col);
    float4 v_bhn = *(const float4*)(bhn + col);

    float4 o;
    {
        float r = sigmoidf_(vr.x + v_bir.x);
        float z = sigmoidf_(vz.x + v_biz.x);
        float n = tanhf(vp.x + v_bin.x + r * (vh.x + v_bhn.x));
        o.x = (1.f - z) * n + z * he.x;
    }
    {
        float r = sigmoidf_(vr.y + v_bir.y);
        float z = sigmoidf_(vz.y + v_biz.y);
        float n = tanhf(vp.y + v_bin.y + r * (vh.y + v_bhn.y));
        o.y = (1.f - z) * n + z * he.y;
    }
    {
        float r = sigmoidf_(vr.z + v_bir.z);
        float z = sigmoidf_(vz.z + v_biz.z);
        float n = tanhf(vp.z + v_bin.z + r * (vh.z + v_bhn.z));
        o.z = (1.f - z) * n + z * he.z;
    }
    {
        float r = sigmoidf_(vr.w + v_bir.w);
        float z = sigmoidf_(vz.w + v_biz.w);
        float n = tanhf(vp.w + v_bin.w + r * (vh.w + v_bhn.w));
        o.w = (1.f - z) * n + z * he.w;
    }
    ((float4*)out)[i4] = o;
}

/* ---------------- launch --------------------------------------------------- */
extern "C" void kernel_launch(void* const* d_in, const int* in_sizes, int n_in,
                              void* d_out, int out_size)
{
    int s = (n_in >= 18) ? 2 : 0;

    const float* emb    = (const float*)d_in[0];
    const int*   src    = (const int*)d_in[1];
    const int*   dst    = (const int*)d_in[2];
    const int*   et     = (const int*)d_in[3];
    const float* W_edge = (const float*)d_in[4 + s];
    const float* b_edge = (const float*)d_in[5 + s];
    const float* Wir    = (const float*)d_in[6 + s];
    const float* Wiz    = (const float*)d_in[7 + s];
    const float* Win    = (const float*)d_in[8 + s];
    const float* bir    = (const float*)d_in[9 + s];
    const float* biz    = (const float*)d_in[10 + s];
    const float* bin    = (const float*)d_in[11 + s];
    const float* Whr    = (const float*)d_in[12 + s];
    const float* Whz    = (const float*)d_in[13 + s];
    const float* Whn    = (const float*)d_in[14 + s];
    const float* bhn    = (const float*)d_in[15 + s];
    float* out = (float*)d_out;

    float* d_prop; cudaGetSymbolAddress((void**)&d_prop, g_proposed);
    float* d_rr;   cudaGetSymbolAddress((void**)&d_rr, g_rr);
    float* d_zz;   cudaGetSymbolAddress((void**)&d_zz, g_zz);
    float* d_np;   cudaGetSymbolAddress((void**)&d_np, g_np);
    float* d_nh;   cudaGetSymbolAddress((void**)&d_nh, g_nh);

    k_init_proposed<<<(NN * HH / 4 + 255) / 256, 256>>>();
    k_init_meta<<<(SORT_CAP + 255) / 256, 256>>>();
    k_hist<<<(EE + 255) / 256, 256>>>(et);
    k_offsets<<<1, 32>>>();
    k_scatter<<<(EE + 255) / 256, 256>>>(et);

    dim3 eg((EE + TT * 128 + 127) / 128, HH / 64);
    k_edge_gemm<<<eg, 256>>>(emb, src, dst, W_edge, b_edge);

    dim3 gg(MPAD / 128, HH / 64);
    k_gemm2<<<gg, 256>>>(d_prop, Wir, emb, Whr, d_rr);
    k_gemm2<<<gg, 256>>>(d_prop, Wiz, emb, Whz, d_zz);
    k_gemm1<<<gg, 256>>>(d_prop, Win, d_np);
    k_gemm1<<<gg, 256>>>(emb, Whn, d_nh);

    k_gates<<<(NN * HH / 4 + 255) / 256, 256>>>(emb, bir, biz, bin, bhn, out);
}

// round 4
// speedup vs baseline: 2.3501x; 1.3496x over previous
#include <cuda_runtime.h>
#include <cstdint>
#include <math.h>

#define NN 50000
#define EE 100000
#define HH 512
#define TT 6
#define MBLK 391                       /* ceil(NN/128) */
#define EGRP 788                       /* ceil((EE + TT*128)/128) */
#define SORT_CAP (EE + TT * 128)

#define AST 40                         /* u32 stride per row in smem tiles */
#define A_U32 (128 * AST)              /* 5120 u32 = 20480 B per A matrix  */
#define B_U32 (64 * AST)               /* 2560 u32 = 10240 B per B chunk   */
#define GRU_STAGE_U32 (2 * A_U32 + 6 * B_U32)     /* 25600 u32 = 102400 B */
#define GRU_SMEM (1024 + 2 * GRU_STAGE_U32 * 4)   /* 205824 B             */
#define EDGE_STAGE_U32 (A_U32 + B_U32)            /* 7680 u32 = 30720 B   */
#define EDGE_SMEM (1536 + 2 * EDGE_STAGE_U32 * 4) /* 62976 B              */

/* ---------------- static device scratch ----------------------------------- */
__device__ float    g_proposed[(size_t)NN * HH];
__device__ unsigned g_wswg[(size_t)6 * 8 * 16 * B_U32];   /* GRU weights   */
__device__ unsigned g_wswe[(size_t)48 * 16 * B_U32];      /* edge weights  */
__device__ int g_sorted[SORT_CAP];
__device__ int g_tcount[TT];
__device__ int g_tcur[TT];
__device__ int g_toff[TT + 1];

/* ---------------- helpers -------------------------------------------------- */
__device__ __forceinline__ unsigned f2t(float f) {
    unsigned u;
    asm("cvt.rna.tf32.f32 %0, %1;" : "=r"(u) : "f"(f));
    return u;
}
__device__ __forceinline__ float sigmoidf_(float x) { return 1.0f / (1.0f + expf(-x)); }

__device__ __forceinline__ void mma8(float c[4], uint2 al, uint2 ah, uint2 b) {
    asm volatile(
        "mma.sync.aligned.m16n8k8.row.col.f32.tf32.tf32.f32 "
        "{%0,%1,%2,%3},{%4,%5,%6,%7},{%8,%9},{%0,%1,%2,%3};"
        : "+f"(c[0]), "+f"(c[1]), "+f"(c[2]), "+f"(c[3])
        : "r"(al.x), "r"(ah.x), "r"(al.y), "r"(ah.y), "r"(b.x), "r"(b.y));
}

#define CPA16(d, s) asm volatile("cp.async.ca.shared.global [%0], [%1], 16;" :: "r"(d), "l"(s))
#define CPA_COMMIT() asm volatile("cp.async.commit_group;" ::: "memory")
#define CPA_WAIT0()  asm volatile("cp.async.wait_group 0;" ::: "memory")

__device__ __forceinline__ uint32_t smem_u32(const void* p) {
    uint32_t a;
    asm("{ .reg .u64 t; cvta.to.shared.u64 t, %1; cvt.u32.u64 %0, t; }" : "=r"(a) : "l"(p));
    return a;
}

/* ---------------- small kernels -------------------------------------------- */
__global__ void k_init_proposed() {
    size_t i = (size_t)blockIdx.x * blockDim.x + threadIdx.x;
    size_t n4 = (size_t)NN * HH / 4;
    if (i < n4) ((float4*)g_proposed)[i] = make_float4(0.f, 0.f, 0.f, 0.f);
}
__global__ void k_init_meta() {
    int i = blockIdx.x * blockDim.x + threadIdx.x;
    if (i < TT) { g_tcount[i] = 0; g_tcur[i] = 0; }
    if (i < SORT_CAP) g_sorted[i] = -1;
}
__global__ void k_hist(const int* __restrict__ et) {
    int e = blockIdx.x * blockDim.x + threadIdx.x;
    if (e < EE) atomicAdd(&g_tcount[et[e]], 1);
}
__global__ void k_offsets() {
    if (threadIdx.x == 0 && blockIdx.x == 0) {
        int off = 0;
        for (int t = 0; t < TT; t++) {
            g_toff[t] = off;
            off += ((g_tcount[t] + 127) >> 7) << 7;
        }
        g_toff[TT] = off;
    }
}
__global__ void k_scatter(const int* __restrict__ et) {
    int e = blockIdx.x * blockDim.x + threadIdx.x;
    if (e < EE) {
        int t = et[e];
        int pos = g_toff[t] + atomicAdd(&g_tcur[t], 1);
        g_sorted[pos] = e;
    }
}

/* ---------------- weight prep: tf32 + pair-interleaved layout --------------
 * blob[(...)][n*AST + grp*8 + (k8&3)*2 + (k8>>2)] = tf32(W[k][col])          */
__global__ void k_prep_gru(const float* __restrict__ W0, const float* __restrict__ W1,
                           const float* __restrict__ W2, const float* __restrict__ W3,
                           const float* __restrict__ W4, const float* __restrict__ W5) {
    int kc = blockIdx.x, jb = blockIdx.y, mat = blockIdx.z;
    const float* Ws[6] = {W0, W1, W2, W3, W4, W5};
    const float* W = Ws[mat];
    int tid = threadIdx.x, n = tid & 63, kg = tid >> 6;
    unsigned* dst = &g_wswg[(size_t)((mat * 8 + jb) * 16 + kc) * B_U32];
#pragma unroll
    for (int ii = 0; ii < 8; ii++) {
        int kk = kg * 8 + ii;
        float v = W[(size_t)(kc * 32 + kk) * HH + jb * 64 + n];
        dst[n * AST + kg * 8 + (ii & 3) * 2 + (ii >> 2)] = f2t(v);
    }
}
__global__ void k_prep_edge(const float* __restrict__ W) {
    int kc = blockIdx.x, jb = blockIdx.y;     /* jb 0..47 over 3072 cols */
    int tid = threadIdx.x, n = tid & 63, kg = tid >> 6;
    unsigned* dst = &g_wswe[(size_t)(jb * 16 + kc) * B_U32];
#pragma unroll
    for (int ii = 0; ii < 8; ii++) {
        int kk = kg * 8 + ii;
        float v = W[(size_t)(kc * 32 + kk) * (TT * HH) + jb * 64 + n];
        dst[n * AST + kg * 8 + (ii & 3) * 2 + (ii >> 2)] = f2t(v);
    }
}

/* ---------------- A staging helpers --------------------------------------- */
__device__ __forceinline__ void sts_amat(unsigned* Adst, int tid, const float4* pf) {
#pragma unroll
    for (int i = 0; i < 4; i++) {
        int idx = i * 256 + tid, row = idx >> 3, q = idx & 7;
        unsigned* d = Adst + row * AST + (q >> 1) * 8 + (q & 1);
        d[0] = f2t(pf[i].x); d[2] = f2t(pf[i].y);
        d[4] = f2t(pf[i].z); d[6] = f2t(pf[i].w);
    }
}

/* ---------------- fused GRU mma kernel -------------------------------------
 * grid (8, MBLK): x = col block jb, y = node block. 256 thr, 8 warps 32x32. */
__global__ __launch_bounds__(256, 1) void k_gru_mma(
    const float* __restrict__ emb,
    const float* __restrict__ bir, const float* __restrict__ biz,
    const float* __restrict__ bin, const float* __restrict__ bhn,
    float* __restrict__ out)
{
    extern __shared__ unsigned smu[];
    float* bias_s = (float*)smu;                       /* 256 floats       */
    unsigned* stage0 = smu + 256;
    uint32_t smb = smem_u32(stage0);

    int tid = threadIdx.x, lane = tid & 31, warp = tid >> 5;
    int gid = lane >> 2, tig = lane & 3;
    int wm = (warp >> 1) * 32, wn = (warp & 1) * 32;
    int jb = blockIdx.x, m0 = blockIdx.y * 128;

    {   /* bias slice */
        const float* ba[4] = {bir, biz, bin, bhn};
        bias_s[tid] = ba[tid >> 6][jb * 64 + (tid & 63)];
    }

    float accR[2][4][4], accZ[2][4][4], accN[2][4][4], accH[2][4][4];
#pragma unroll
    for (int mf = 0; mf < 2; mf++)
#pragma unroll
        for (int ni = 0; ni < 4; ni++)
#pragma unroll
            for (int q = 0; q < 4; q++) {
                accR[mf][ni][q] = 0.f; accZ[mf][ni][q] = 0.f;
                accN[mf][ni][q] = 0.f; accH[mf][ni][q] = 0.f;
            }

    /* prologue: fill stage 0 with chunk 0 */
    float4 pf[8];
    {
#pragma unroll
        for (int i = 0; i < 4; i++) {
            int idx = i * 256 + tid, row = idx >> 3, q = idx & 7;
            int r = m0 + row; if (r > NN - 1) r = NN - 1;
            pf[i]     = *(const float4*)(g_proposed + (size_t)r * HH + q * 4);
            pf[4 + i] = *(const float4*)(emb        + (size_t)r * HH + q * 4);
        }
        sts_amat(stage0, tid, pf);
        sts_amat(stage0 + A_U32, tid, pf + 4);
        uint32_t bdst = smb + 2 * A_U32 * 4;
#pragma unroll
        for (int m_ = 0; m_ < 6; m_++) {
            const char* src = (const char*)&g_wswg[(size_t)((m_ * 8 + jb) * 16 + 0) * B_U32];
#pragma unroll
            for (int i = 0; i < 3; i++) {
                int idx = i * 256 + tid;
                if (idx < 640) CPA16(bdst + m_ * 10240 + idx * 16, src + idx * 16);
            }
        }
        CPA_COMMIT(); CPA_WAIT0();
    }
    __syncthreads();

    for (int c = 0; c < 16; c++) {
        unsigned* cur = stage0 + (c & 1) * GRU_STAGE_U32;
        unsigned* nxt = stage0 + ((c & 1) ^ 1) * GRU_STAGE_U32;

        if (c < 15) {   /* issue next-chunk B cp.async + A LDG before compute */
            uint32_t bdst = smem_u32(nxt + 2 * A_U32);
#pragma unroll
            for (int m_ = 0; m_ < 6; m_++) {
                const char* src = (const char*)&g_wswg[(size_t)((m_ * 8 + jb) * 16 + (c + 1)) * B_U32];
#pragma unroll
                for (int i = 0; i < 3; i++) {
                    int idx = i * 256 + tid;
                    if (idx < 640) CPA16(bdst + m_ * 10240 + idx * 16, src + idx * 16);
                }
            }
            CPA_COMMIT();
            int k0 = (c + 1) * 32;
#pragma unroll
            for (int i = 0; i < 4; i++) {
                int idx = i * 256 + tid, row = idx >> 3, q = idx & 7;
                int r = m0 + row; if (r > NN - 1) r = NN - 1;
                pf[i]     = *(const float4*)(g_proposed + (size_t)r * HH + k0 + q * 4);
                pf[4 + i] = *(const float4*)(emb        + (size_t)r * HH + k0 + q * 4);
            }
        }

        /* compute 4 k-steps on cur */
        const unsigned* Ap = cur;
        const unsigned* Ah = cur + A_U32;
        const unsigned* Bb = cur + 2 * A_U32;
#pragma unroll
        for (int ks = 0; ks < 4; ks++) {
            int ko = ks * 8 + tig * 2;
            uint2 apl[2], aph[2], ahl[2], ahh[2];
#pragma unroll
            for (int mf = 0; mf < 2; mf++) {
                int r0 = wm + mf * 16 + gid;
                apl[mf] = *(const uint2*)(Ap + r0 * AST + ko);
                aph[mf] = *(const uint2*)(Ap + (r0 + 8) * AST + ko);
                ahl[mf] = *(const uint2*)(Ah + r0 * AST + ko);
                ahh[mf] = *(const uint2*)(Ah + (r0 + 8) * AST + ko);
            }
#pragma unroll
            for (int ni = 0; ni < 4; ni++) {
                int cb = (wn + ni * 8 + gid) * AST + ko;
                uint2 b;
                b = *(const uint2*)(Bb + 0 * B_U32 + cb);   /* Wir */
#pragma unroll
                for (int mf = 0; mf < 2; mf++) mma8(accR[mf][ni], apl[mf], aph[mf], b);
                b = *(const uint2*)(Bb + 1 * B_U32 + cb);   /* Whr */
#pragma unroll
                for (int mf = 0; mf < 2; mf++) mma8(accR[mf][ni], ahl[mf], ahh[mf], b);
                b = *(const uint2*)(Bb + 2 * B_U32 + cb);   /* Wiz */
#pragma unroll
                for (int mf = 0; mf < 2; mf++) mma8(accZ[mf][ni], apl[mf], aph[mf], b);
                b = *(const uint2*)(Bb + 3 * B_U32 + cb);   /* Whz */
#pragma unroll
                for (int mf = 0; mf < 2; mf++) mma8(accZ[mf][ni], ahl[mf], ahh[mf], b);
                b = *(const uint2*)(Bb + 4 * B_U32 + cb);   /* Win */
#pragma unroll
                for (int mf = 0; mf < 2; mf++) mma8(accN[mf][ni], apl[mf], aph[mf], b);
                b = *(const uint2*)(Bb + 5 * B_U32 + cb);   /* Whn */
#pragma unroll
                for (int mf = 0; mf < 2; mf++) mma8(accH[mf][ni], ahl[mf], ahh[mf], b);
            }
        }

        if (c < 15) {
            sts_amat(nxt, tid, pf);
            sts_amat(nxt + A_U32, tid, pf + 4);
            CPA_WAIT0();
        }
        __syncthreads();
    }

    /* epilogue: gates */
#pragma unroll
    for (int mf = 0; mf < 2; mf++) {
#pragma unroll
        for (int rp = 0; rp < 2; rp++) {
            int lrow = wm + mf * 16 + rp * 8 + gid;
            int row = m0 + lrow;
            if (row >= NN) continue;
            const float* hrow = emb + (size_t)row * HH + jb * 64;
            float* orow = out + (size_t)row * HH + jb * 64;
#pragma unroll
            for (int ni = 0; ni < 4; ni++) {
                int c0 = wn + ni * 8 + tig * 2;
                float2 h2 = *(const float2*)(hrow + c0);
                float o[2];
#pragma unroll
                for (int e = 0; e < 2; e++) {
                    int q = rp * 2 + e;
                    int cl = c0 + e;
                    float r = sigmoidf_(accR[mf][ni][q] + bias_s[cl]);
                    float z = sigmoidf_(accZ[mf][ni][q] + bias_s[64 + cl]);
                    float n = tanhf(accN[mf][ni][q] + bias_s[128 + cl]
                                    + r * (accH[mf][ni][q] + bias_s[192 + cl]));
                    float h = e ? h2.y : h2.x;
                    o[e] = (1.f - z) * n + z * h;
                }
                *(float2*)(orow + c0) = make_float2(o[0], o[1]);
            }
        }
    }
}

/* ---------------- edge mma kernel ------------------------------------------
 * grid (8, EGRP): x = jb within the type's 512 cols, y = 128-edge group.   */
__global__ __launch_bounds__(256, 2) void k_edge_mma(
    const float* __restrict__ emb, const int* __restrict__ src,
    const int* __restrict__ dst, const float* __restrict__ b_edge)
{
    int start = blockIdx.y * 128;
    if (start >= g_toff[TT]) return;
    int t = 0;
#pragma unroll
    for (int i = 1; i < TT; i++) if (start >= g_toff[i]) t = i;
    int jb8 = blockIdx.x;
    int jbg = t * 8 + jb8;             /* global col-block 0..47 */

    extern __shared__ unsigned smu[];
    int* s_srow = (int*)smu;           /* 128 */
    int* s_dst  = (int*)smu + 128;     /* 128 */
    float* s_bias = (float*)smu + 256; /* 64  */
    unsigned* stage0 = smu + 384;

    int tid = threadIdx.x, lane = tid & 31, warp = tid >> 5;
    int gid = lane >> 2, tig = lane & 3;
    int wm = (warp >> 1) * 32, wn = (warp & 1) * 32;

    if (tid < 128) {
        int e = g_sorted[start + tid];
        s_srow[tid] = (e >= 0) ? src[e] : -1;
        s_dst[tid]  = (e >= 0) ? dst[e] : -1;
    }
    if (tid < 64) s_bias[tid] = b_edge[(size_t)t * HH + jb8 * 64 + tid];
    __syncthreads();

    float acc[2][4][4];
#pragma unroll
    for (int mf = 0; mf < 2; mf++)
#pragma unroll
        for (int ni = 0; ni < 4; ni++)
#pragma unroll
            for (int q = 0; q < 4; q++) acc[mf][ni][q] = 0.f;

    float4 pf[4];
    {
#pragma unroll
        for (int i = 0; i < 4; i++) {
            int idx = i * 256 + tid, row = idx >> 3, q = idx & 7;
            int nr = s_srow[row];
            pf[i] = (nr >= 0) ? *(const float4*)(emb + (size_t)nr * HH + q * 4)
                              : make_float4(0.f, 0.f, 0.f, 0.f);
        }
        sts_amat(stage0, tid, pf);
        uint32_t bdst = smem_u32(stage0 + A_U32);
        const char* srcb = (const char*)&g_wswe[(size_t)(jbg * 16 + 0) * B_U32];
#pragma unroll
        for (int i = 0; i < 3; i++) {
            int idx = i * 256 + tid;
            if (idx < 640) CPA16(bdst + idx * 16, srcb + idx * 16);
        }
        CPA_COMMIT(); CPA_WAIT0();
    }
    __syncthreads();

    for (int c = 0; c < 16; c++) {
        unsigned* cur = stage0 + (c & 1) * EDGE_STAGE_U32;
        unsigned* nxt = stage0 + ((c & 1) ^ 1) * EDGE_STAGE_U32;

        if (c < 15) {
            uint32_t bdst = smem_u32(nxt + A_U32);
            const char* srcb = (const char*)&g_wswe[(size_t)(jbg * 16 + (c + 1)) * B_U32];
#pragma unroll
            for (int i = 0; i < 3; i++) {
                int idx = i * 256 + tid;
                if (idx < 640) CPA16(bdst + idx * 16, srcb + idx * 16);
            }
            CPA_COMMIT();
            int k0 = (c + 1) * 32;
#pragma unroll
            for (int i = 0; i < 4; i++) {
                int idx = i * 256 + tid, row = idx >> 3, q = idx & 7;
                int nr = s_srow[row];
                pf[i] = (nr >= 0) ? *(const float4*)(emb + (size_t)nr * HH + k0 + q * 4)
                                  : make_float4(0.f, 0.f, 0.f, 0.f);
            }
        }

        const unsigned* Ap = cur;
        const unsigned* Bb = cur + A_U32;
#pragma unroll
        for (int ks = 0; ks < 4; ks++) {
            int ko = ks * 8 + tig * 2;
            uint2 apl[2], aph[2];
#pragma unroll
            for (int mf = 0; mf < 2; mf++) {
                int r0 = wm + mf * 16 + gid;
                apl[mf] = *(const uint2*)(Ap + r0 * AST + ko);
                aph[mf] = *(const uint2*)(Ap + (r0 + 8) * AST + ko);
            }
#pragma unroll
            for (int ni = 0; ni < 4; ni++) {
                uint2 b = *(const uint2*)(Bb + (wn + ni * 8 + gid) * AST + ko);
#pragma unroll
                for (int mf = 0; mf < 2; mf++) mma8(acc[mf][ni], apl[mf], aph[mf], b);
            }
        }

        if (c < 15) {
            sts_amat(nxt, tid, pf);
            CPA_WAIT0();
        }
        __syncthreads();
    }

    /* epilogue: bias + atomic scatter-add */
#pragma unroll
    for (int mf = 0; mf < 2; mf++) {
#pragma unroll
        for (int rp = 0; rp < 2; rp++) {
            int arow = wm + mf * 16 + rp * 8 + gid;
            int d = s_dst[arow];
            if (d < 0) continue;
            float* prow = g_proposed + (size_t)d * HH + jb8 * 64;
#pragma unroll
            for (int ni = 0; ni < 4; ni++) {
                int c0 = wn + ni * 8 + tig * 2;
                atomicAdd(prow + c0,     acc[mf][ni][rp * 2]     + s_bias[c0]);
                atomicAdd(prow + c0 + 1, acc[mf][ni][rp * 2 + 1] + s_bias[c0 + 1]);
            }
        }
    }
}

/* ---------------- launch --------------------------------------------------- */
extern "C" void kernel_launch(void* const* d_in, const int* in_sizes, int n_in,
                              void* d_out, int out_size)
{
    int s = (n_in >= 18) ? 2 : 0;

    const float* emb    = (const float*)d_in[0];
    const int*   src    = (const int*)d_in[1];
    const int*   dst    = (const int*)d_in[2];
    const int*   et     = (const int*)d_in[3];
    const float* W_edge = (const float*)d_in[4 + s];
    const float* b_edge = (const float*)d_in[5 + s];
    const float* Wir    = (const float*)d_in[6 + s];
    const float* Wiz    = (const float*)d_in[7 + s];
    const float* Win    = (const float*)d_in[8 + s];
    const float* bir    = (const float*)d_in[9 + s];
    const float* biz    = (const float*)d_in[10 + s];
    const float* bin    = (const float*)d_in[11 + s];
    const float* Whr    = (const float*)d_in[12 + s];
    const float* Whz    = (const float*)d_in[13 + s];
    const float* Whn    = (const float*)d_in[14 + s];
    const float* bhn    = (const float*)d_in[15 + s];
    float* out = (float*)d_out;

    static int attr_done = 0;
    if (!attr_done) {
        cudaFuncSetAttribute(k_gru_mma,  cudaFuncAttributeMaxDynamicSharedMemorySize, GRU_SMEM);
        cudaFuncSetAttribute(k_edge_mma, cudaFuncAttributeMaxDynamicSharedMemorySize, EDGE_SMEM);
        attr_done = 1;
    }

    k_init_proposed<<<(NN * HH / 4 + 255) / 256, 256>>>();
    k_init_meta<<<(SORT_CAP + 255) / 256, 256>>>();
    k_hist<<<(EE + 255) / 256, 256>>>(et);
    k_offsets<<<1, 32>>>();
    k_scatter<<<(EE + 255) / 256, 256>>>(et);

    k_prep_gru<<<dim3(16, 8, 6), 256>>>(Wir, Whr, Wiz, Whz, Win, Whn);
    k_prep_edge<<<dim3(16, 48), 256>>>(W_edge);

    k_edge_mma<<<dim3(8, EGRP), 256, EDGE_SMEM>>>(emb, src, dst, b_edge);
    k_gru_mma<<<dim3(8, MBLK), 256, GRU_SMEM>>>(emb, bir, biz, bin, bhn, out);
}

// round 5
// speedup vs baseline: 3.0151x; 1.2829x over previous
#include <cuda_runtime.h>
#include <cstdint>
#include <math.h>

#define NN 50000
#define EE 100000
#define HH 512
#define TT 6
#define MBLK 391                       /* ceil(NN/128) */
#define EGRP 788                       /* ceil((EE + TT*128)/128) */
#define SORT_CAP (EE + TT * 128)

#define ASTR 36                        /* u32 stride of raw-A rows (32 + pad) */
#define BSTR 40                        /* u32 stride of tf32-B rows           */
#define B_U32 (64 * BSTR)              /* 2560 u32 = 10240 B per B chunk      */

/* GRU: stage = Ap(128*36) + Ah(128*36) + 6*B = 9216 + 15360 = 24576 u32 */
#define GRU_A_U32   (128 * ASTR)
#define GRU_BOFF    (2 * GRU_A_U32)
#define GRU_STAGE_U32 (GRU_BOFF + 6 * B_U32)
#define GRU_SMEM    (1024 + 2 * GRU_STAGE_U32 * 4)      /* 197632 B */

/* EDGE: stage = A(128*36) + B = 4608 + 2560 = 7168 u32 */
#define EDGE_STAGE_U32 (GRU_A_U32 + B_U32)
#define EDGE_SMEM   (1536 + 2 * EDGE_STAGE_U32 * 4)     /* 58880 B  */

/* ---------------- static device scratch ----------------------------------- */
__device__ float    g_proposed[(size_t)NN * HH];
__device__ unsigned g_wswg[(size_t)6 * 8 * 16 * B_U32];
__device__ unsigned g_wswe[(size_t)48 * 16 * B_U32];
__device__ int g_sorted[SORT_CAP];
__device__ int g_tcount[TT];
__device__ int g_tcur[TT];
__device__ int g_toff[TT + 1];

/* ---------------- helpers -------------------------------------------------- */
__device__ __forceinline__ unsigned f2t(float f) {
    unsigned u;
    asm("cvt.rna.tf32.f32 %0, %1;" : "=r"(u) : "f"(f));
    return u;
}
__device__ __forceinline__ float sigmoidf_(float x) { return 1.0f / (1.0f + expf(-x)); }

__device__ __forceinline__ void mma4(float c[4], const unsigned a[4], uint2 b) {
    asm volatile(
        "mma.sync.aligned.m16n8k8.row.col.f32.tf32.tf32.f32 "
        "{%0,%1,%2,%3},{%4,%5,%6,%7},{%8,%9},{%0,%1,%2,%3};"
        : "+f"(c[0]), "+f"(c[1]), "+f"(c[2]), "+f"(c[3])
        : "r"(a[0]), "r"(a[1]), "r"(a[2]), "r"(a[3]), "r"(b.x), "r"(b.y));
}

#define CPA16(d, s) asm volatile("cp.async.ca.shared.global [%0], [%1], 16;" :: "r"(d), "l"(s))
#define CPA_COMMIT() asm volatile("cp.async.commit_group;" ::: "memory")
#define CPA_WAIT0()  asm volatile("cp.async.wait_group 0;" ::: "memory")

__device__ __forceinline__ uint32_t smem_u32(const void* p) {
    uint32_t a;
    asm("{ .reg .u64 t; cvta.to.shared.u64 t, %1; cvt.u32.u64 %0, t; }" : "=r"(a) : "l"(p));
    return a;
}

/* ---------------- small kernels -------------------------------------------- */
__global__ void k_init_proposed() {
    size_t i = (size_t)blockIdx.x * blockDim.x + threadIdx.x;
    size_t n4 = (size_t)NN * HH / 4;
    if (i < n4) ((float4*)g_proposed)[i] = make_float4(0.f, 0.f, 0.f, 0.f);
}
__global__ void k_init_meta() {
    int i = blockIdx.x * blockDim.x + threadIdx.x;
    if (i < TT) { g_tcount[i] = 0; g_tcur[i] = 0; }
    if (i < SORT_CAP) g_sorted[i] = -1;
}
__global__ void k_hist(const int* __restrict__ et) {
    int e = blockIdx.x * blockDim.x + threadIdx.x;
    if (e < EE) atomicAdd(&g_tcount[et[e]], 1);
}
__global__ void k_offsets() {
    if (threadIdx.x == 0 && blockIdx.x == 0) {
        int off = 0;
        for (int t = 0; t < TT; t++) {
            g_toff[t] = off;
            off += ((g_tcount[t] + 127) >> 7) << 7;
        }
        g_toff[TT] = off;
    }
}
__global__ void k_scatter(const int* __restrict__ et) {
    int e = blockIdx.x * blockDim.x + threadIdx.x;
    if (e < EE) {
        int t = et[e];
        int pos = g_toff[t] + atomicAdd(&g_tcur[t], 1);
        g_sorted[pos] = e;
    }
}

/* ---------------- weight prep: tf32 + pair-interleaved layout --------------
 * pos p in each 8-k group holds k = (p&1)*4 + (p>>1); frag LDS.64 at
 * tig*2 yields (k=tig, k=tig+4) = canonical m16n8k8 B fragment.             */
__global__ void k_prep_gru(const float* __restrict__ W0, const float* __restrict__ W1,
                           const float* __restrict__ W2, const float* __restrict__ W3,
                           const float* __restrict__ W4, const float* __restrict__ W5) {
    int kc = blockIdx.x, jb = blockIdx.y, mat = blockIdx.z;
    const float* Ws[6] = {W0, W1, W2, W3, W4, W5};
    const float* W = Ws[mat];
    int tid = threadIdx.x, n = tid & 63, kg = tid >> 6;
    unsigned* dst = &g_wswg[(size_t)((mat * 8 + jb) * 16 + kc) * B_U32];
#pragma unroll
    for (int ii = 0; ii < 8; ii++) {
        int kk = kg * 8 + ii;
        float v = W[(size_t)(kc * 32 + kk) * HH + jb * 64 + n];
        dst[n * BSTR + kg * 8 + (ii & 3) * 2 + (ii >> 2)] = f2t(v);
    }
}
__global__ void k_prep_edge(const float* __restrict__ W) {
    int kc = blockIdx.x, jb = blockIdx.y;     /* jb 0..47 over 3072 cols */
    int tid = threadIdx.x, n = tid & 63, kg = tid >> 6;
    unsigned* dst = &g_wswe[(size_t)(jb * 16 + kc) * B_U32];
#pragma unroll
    for (int ii = 0; ii < 8; ii++) {
        int kk = kg * 8 + ii;
        float v = W[(size_t)(kc * 32 + kk) * (TT * HH) + jb * 64 + n];
        dst[n * BSTR + kg * 8 + (ii & 3) * 2 + (ii >> 2)] = f2t(v);
    }
}

/* ---------------- fused GRU mma kernel -------------------------------------
 * 512 threads, 16 warps, warp tile 32x16, CTA tile 128x64.
 * A (proposed & emb) raw fp32 via cp.async; tf32 cvt at fragment load.      */
__device__ __forceinline__ void gru_fill(uint32_t st, const float* __restrict__ P,
                                         const float* __restrict__ Hm,
                                         int m0, int k0, int jb, int kc, int tid)
{
#pragma unroll
    for (int m_ = 0; m_ < 6; m_++) {
        const char* src = (const char*)&g_wswg[(size_t)((m_ * 8 + jb) * 16 + kc) * B_U32];
        uint32_t d0 = st + (GRU_BOFF + m_ * B_U32) * 4;
        CPA16(d0 + tid * 16, src + tid * 16);
        if (tid < 128) CPA16(d0 + (512 + tid) * 16, src + (512 + tid) * 16);
    }
#pragma unroll
    for (int i = 0; i < 4; i++) {
        int idx = i * 512 + tid;
        int mat = idx >> 10, r = (idx >> 3) & 127, q = idx & 7;
        int rg = m0 + r; if (rg > NN - 1) rg = NN - 1;
        const float* s = (mat ? Hm : P) + (size_t)rg * HH + k0 + q * 4;
        CPA16(st + (mat * GRU_A_U32 + r * ASTR + q * 4) * 4, s);
    }
    CPA_COMMIT();
}

__global__ __launch_bounds__(512, 1) void k_gru_mma(
    const float* __restrict__ emb,
    const float* __restrict__ bir, const float* __restrict__ biz,
    const float* __restrict__ bin, const float* __restrict__ bhn,
    float* __restrict__ out)
{
    extern __shared__ unsigned smu[];
    float* bias_s = (float*)smu;                 /* 256 floats */
    unsigned* stage0 = smu + 256;
    uint32_t st0 = smem_u32(stage0);

    int tid = threadIdx.x, lane = tid & 31, warp = tid >> 5;
    int gid = lane >> 2, tig = lane & 3;
    int wm = (warp >> 2) * 32, wn = (warp & 3) * 16;
    int jb = blockIdx.x, m0 = blockIdx.y * 128;

    if (tid < 256) {
        const float* ba[4] = {bir, biz, bin, bhn};
        bias_s[tid] = ba[tid >> 6][jb * 64 + (tid & 63)];
    }

    float accR[2][2][4], accZ[2][2][4], accN[2][2][4], accH[2][2][4];
#pragma unroll
    for (int mf = 0; mf < 2; mf++)
#pragma unroll
        for (int ni = 0; ni < 2; ni++)
#pragma unroll
            for (int q = 0; q < 4; q++) {
                accR[mf][ni][q] = 0.f; accZ[mf][ni][q] = 0.f;
                accN[mf][ni][q] = 0.f; accH[mf][ni][q] = 0.f;
            }

    gru_fill(st0, g_proposed, emb, m0, 0, jb, 0, tid);
    CPA_WAIT0();
    __syncthreads();

    for (int c = 0; c < 16; c++) {
        const unsigned* cur = stage0 + (c & 1) * GRU_STAGE_U32;

        if (c < 15)
            gru_fill(st0 + ((c & 1) ^ 1) * GRU_STAGE_U32 * 4,
                     g_proposed, emb, m0, (c + 1) * 32, jb, c + 1, tid);

        const float* Af = (const float*)cur;
        const unsigned* Bb = cur + GRU_BOFF;
#pragma unroll
        for (int ks = 0; ks < 4; ks++) {
            int kk = ks * 8 + tig;
            unsigned ap[2][4], ah[2][4];
#pragma unroll
            for (int mf = 0; mf < 2; mf++) {
                int r0 = wm + mf * 16 + gid;
                ap[mf][0] = f2t(Af[r0 * ASTR + kk]);
                ap[mf][1] = f2t(Af[(r0 + 8) * ASTR + kk]);
                ap[mf][2] = f2t(Af[r0 * ASTR + kk + 4]);
                ap[mf][3] = f2t(Af[(r0 + 8) * ASTR + kk + 4]);
                ah[mf][0] = f2t(Af[GRU_A_U32 + r0 * ASTR + kk]);
                ah[mf][1] = f2t(Af[GRU_A_U32 + (r0 + 8) * ASTR + kk]);
                ah[mf][2] = f2t(Af[GRU_A_U32 + r0 * ASTR + kk + 4]);
                ah[mf][3] = f2t(Af[GRU_A_U32 + (r0 + 8) * ASTR + kk + 4]);
            }
#pragma unroll
            for (int ni = 0; ni < 2; ni++) {
                int cb = (wn + ni * 8 + gid) * BSTR + ks * 8 + tig * 2;
                uint2 b;
                b = *(const uint2*)(Bb + 0 * B_U32 + cb);   /* Wir */
#pragma unroll
                for (int mf = 0; mf < 2; mf++) mma4(accR[mf][ni], ap[mf], b);
                b = *(const uint2*)(Bb + 1 * B_U32 + cb);   /* Whr */
#pragma unroll
                for (int mf = 0; mf < 2; mf++) mma4(accR[mf][ni], ah[mf], b);
                b = *(const uint2*)(Bb + 2 * B_U32 + cb);   /* Wiz */
#pragma unroll
                for (int mf = 0; mf < 2; mf++) mma4(accZ[mf][ni], ap[mf], b);
                b = *(const uint2*)(Bb + 3 * B_U32 + cb);   /* Whz */
#pragma unroll
                for (int mf = 0; mf < 2; mf++) mma4(accZ[mf][ni], ah[mf], b);
                b = *(const uint2*)(Bb + 4 * B_U32 + cb);   /* Win */
#pragma unroll
                for (int mf = 0; mf < 2; mf++) mma4(accN[mf][ni], ap[mf], b);
                b = *(const uint2*)(Bb + 5 * B_U32 + cb);   /* Whn */
#pragma unroll
                for (int mf = 0; mf < 2; mf++) mma4(accH[mf][ni], ah[mf], b);
            }
        }
        CPA_WAIT0();
        __syncthreads();
    }

    /* epilogue: gates */
#pragma unroll
    for (int mf = 0; mf < 2; mf++) {
#pragma unroll
        for (int rp = 0; rp < 2; rp++) {
            int row = m0 + wm + mf * 16 + rp * 8 + gid;
            if (row >= NN) continue;
            const float* hrow = emb + (size_t)row * HH + jb * 64;
            float* orow = out + (size_t)row * HH + jb * 64;
#pragma unroll
            for (int ni = 0; ni < 2; ni++) {
                int c0 = wn + ni * 8 + tig * 2;
                float2 h2 = *(const float2*)(hrow + c0);
                float o[2];
#pragma unroll
                for (int e = 0; e < 2; e++) {
                    int q = rp * 2 + e;
                    int cl = c0 + e;
                    float r = sigmoidf_(accR[mf][ni][q] + bias_s[cl]);
                    float z = sigmoidf_(accZ[mf][ni][q] + bias_s[64 + cl]);
                    float n = tanhf(accN[mf][ni][q] + bias_s[128 + cl]
                                    + r * (accH[mf][ni][q] + bias_s[192 + cl]));
                    float h = e ? h2.y : h2.x;
                    o[e] = (1.f - z) * n + z * h;
                }
                *(float2*)(orow + c0) = make_float2(o[0], o[1]);
            }
        }
    }
}

/* ---------------- edge mma kernel ------------------------------------------
 * 256 threads, 8 warps, warp tile 32x32, CTA tile 128x64.                   */
__device__ __forceinline__ void edge_fill(uint32_t st, const float* __restrict__ emb,
                                          const int* __restrict__ ssrc,
                                          int k0, int jbg, int kc, int tid)
{
    const char* src = (const char*)&g_wswe[(size_t)(jbg * 16 + kc) * B_U32];
    uint32_t d0 = st + GRU_A_U32 * 4;
#pragma unroll
    for (int i = 0; i < 3; i++) {
        int idx = i * 256 + tid;
        if (idx < 640) CPA16(d0 + idx * 16, src + idx * 16);
    }
#pragma unroll
    for (int i = 0; i < 4; i++) {
        int idx = i * 256 + tid, r = idx >> 3, q = idx & 7;
        int nr = ssrc[r]; if (nr < 0) nr = 0;
        CPA16(st + (r * ASTR + q * 4) * 4,
              (const void*)(emb + (size_t)nr * HH + k0 + q * 4));
    }
    CPA_COMMIT();
}

__global__ __launch_bounds__(256, 2) void k_edge_mma(
    const float* __restrict__ emb, const int* __restrict__ src,
    const int* __restrict__ dst, const float* __restrict__ b_edge)
{
    int start = blockIdx.y * 128;
    if (start >= g_toff[TT]) return;
    int t = 0;
#pragma unroll
    for (int i = 1; i < TT; i++) if (start >= g_toff[i]) t = i;
    int jb8 = blockIdx.x;
    int jbg = t * 8 + jb8;

    extern __shared__ unsigned smu[];
    int* s_srow = (int*)smu;             /* 128 */
    int* s_dst  = (int*)smu + 128;       /* 128 */
    float* s_bias = (float*)smu + 256;   /* 64  */
    unsigned* stage0 = smu + 384;
    uint32_t st0 = smem_u32(stage0);

    int tid = threadIdx.x, lane = tid & 31, warp = tid >> 5;
    int gid = lane >> 2, tig = lane & 3;
    int wm = (warp >> 1) * 32, wn = (warp & 1) * 32;

    if (tid < 128) {
        int e = g_sorted[start + tid];
        s_srow[tid] = (e >= 0) ? src[e] : -1;
        s_dst[tid]  = (e >= 0) ? dst[e] : -1;
    }
    if (tid < 64) s_bias[tid] = b_edge[(size_t)t * HH + jb8 * 64 + tid];
    __syncthreads();

    float acc[2][4][4];
#pragma unroll
    for (int mf = 0; mf < 2; mf++)
#pragma unroll
        for (int ni = 0; ni < 4; ni++)
#pragma unroll
            for (int q = 0; q < 4; q++) acc[mf][ni][q] = 0.f;

    edge_fill(st0, emb, s_srow, 0, jbg, 0, tid);
    CPA_WAIT0();
    __syncthreads();

    for (int c = 0; c < 16; c++) {
        const unsigned* cur = stage0 + (c & 1) * EDGE_STAGE_U32;

        if (c < 15)
            edge_fill(st0 + ((c & 1) ^ 1) * EDGE_STAGE_U32 * 4,
                      emb, s_srow, (c + 1) * 32, jbg, c + 1, tid);

        const float* Af = (const float*)cur;
        const unsigned* Bb = cur + GRU_A_U32;
#pragma unroll
        for (int ks = 0; ks < 4; ks++) {
            int kk = ks * 8 + tig;
            unsigned ap[2][4];
#pragma unroll
            for (int mf = 0; mf < 2; mf++) {
                int r0 = wm + mf * 16 + gid;
                ap[mf][0] = f2t(Af[r0 * ASTR + kk]);
                ap[mf][1] = f2t(Af[(r0 + 8) * ASTR + kk]);
                ap[mf][2] = f2t(Af[r0 * ASTR + kk + 4]);
                ap[mf][3] = f2t(Af[(r0 + 8) * ASTR + kk + 4]);
            }
#pragma unroll
            for (int ni = 0; ni < 4; ni++) {
                uint2 b = *(const uint2*)(Bb + (wn + ni * 8 + gid) * BSTR + ks * 8 + tig * 2);
#pragma unroll
                for (int mf = 0; mf < 2; mf++) mma4(acc[mf][ni], ap[mf], b);
            }
        }
        CPA_WAIT0();
        __syncthreads();
    }

    /* epilogue: bias + atomic scatter-add */
#pragma unroll
    for (int mf = 0; mf < 2; mf++) {
#pragma unroll
        for (int rp = 0; rp < 2; rp++) {
            int arow = wm + mf * 16 + rp * 8 + gid;
            int d = s_dst[arow];
            if (d < 0) continue;
            float* prow = g_proposed + (size_t)d * HH + jb8 * 64;
#pragma unroll
            for (int ni = 0; ni < 4; ni++) {
                int c0 = wn + ni * 8 + tig * 2;
                atomicAdd(prow + c0,     acc[mf][ni][rp * 2]     + s_bias[c0]);
                atomicAdd(prow + c0 + 1, acc[mf][ni][rp * 2 + 1] + s_bias[c0 + 1]);
            }
        }
    }
}

/* ---------------- launch --------------------------------------------------- */
extern "C" void kernel_launch(void* const* d_in, const int* in_sizes, int n_in,
                              void* d_out, int out_size)
{
    int s = (n_in >= 18) ? 2 : 0;

    const float* emb    = (const float*)d_in[0];
    const int*   src    = (const int*)d_in[1];
    const int*   dst    = (const int*)d_in[2];
    const int*   et     = (const int*)d_in[3];
    const float* W_edge = (const float*)d_in[4 + s];
    const float* b_edge = (const float*)d_in[5 + s];
    const float* Wir    = (const float*)d_in[6 + s];
    const float* Wiz    = (const float*)d_in[7 + s];
    const float* Win    = (const float*)d_in[8 + s];
    const float* bir    = (const float*)d_in[9 + s];
    const float* biz    = (const float*)d_in[10 + s];
    const float* bin    = (const float*)d_in[11 + s];
    const float* Whr    = (const float*)d_in[12 + s];
    const float* Whz    = (const float*)d_in[13 + s];
    const float* Whn    = (const float*)d_in[14 + s];
    const float* bhn    = (const float*)d_in[15 + s];
    float* out = (float*)d_out;

    static int attr_done = 0;
    if (!attr_done) {
        cudaFuncSetAttribute(k_gru_mma,  cudaFuncAttributeMaxDynamicSharedMemorySize, GRU_SMEM);
        cudaFuncSetAttribute(k_edge_mma, cudaFuncAttributeMaxDynamicSharedMemorySize, EDGE_SMEM);
        attr_done = 1;
    }

    k_init_proposed<<<(NN * HH / 4 + 255) / 256, 256>>>();
    k_init_meta<<<(SORT_CAP + 255) / 256, 256>>>();
    k_hist<<<(EE + 255) / 256, 256>>>(et);
    k_offsets<<<1, 32>>>();
    k_scatter<<<(EE + 255) / 256, 256>>>(et);

    k_prep_gru<<<dim3(16, 8, 6), 256>>>(Wir, Whr, Wiz, Whz, Win, Whn);
    k_prep_edge<<<dim3(16, 48), 256>>>(W_edge);

    k_edge_mma<<<dim3(8, EGRP), 256, EDGE_SMEM>>>(emb, src, dst, b_edge);
    k_gru_mma<<<dim3(8, MBLK), 512, GRU_SMEM>>>(emb, bir, biz, bin, bhn, out);
}

// round 6
// speedup vs baseline: 4.1286x; 1.3693x over previous
#include <cuda_runtime.h>
#include <cuda_fp16.h>
#include <cstdint>
#include <math.h>

#define NN 50000
#define EE 100000
#define HH 512
#define TT 6
#define MBLK 391                       /* ceil(NN/128) */
#define EGRP 788                       /* ceil((EE + TT*128)/128) */
#define SORT_CAP (EE + TT * 128)

#define ASTR 40                        /* u32 stride of raw-fp32 A rows       */
#define BSTR 20                        /* u32 stride of fp16-pair B rows      */
#define B_GU32 (64 * 16)               /* global blob: 64 rows x 16 u32       */
#define B_SU32 (64 * BSTR)             /* smem: 64 rows x 20 u32 = 1280       */

#define GRU_A_U32   (128 * ASTR)                        /* 5120 */
#define GRU_BOFF    (2 * GRU_A_U32)                     /* 10240 */
#define GRU_STAGE_U32 (GRU_BOFF + 6 * B_SU32)           /* 17920 */
#define GRU_SMEM    (1024 + 2 * GRU_STAGE_U32 * 4)      /* 144384 B */

#define EDGE_STAGE_U32 (GRU_A_U32 + B_SU32)             /* 6400 */
#define EDGE_SMEM   (1536 + 2 * EDGE_STAGE_U32 * 4)     /* 52736 B */

/* ---------------- static device scratch ----------------------------------- */
__device__ float    g_proposed[(size_t)NN * HH];
__device__ unsigned g_wswg[(size_t)6 * 8 * 16 * B_GU32];
__device__ unsigned g_wswe[(size_t)48 * 16 * B_GU32];
__device__ int g_sorted[SORT_CAP];
__device__ int g_tcount[TT];
__device__ int g_tcur[TT];
__device__ int g_toff[TT + 1];

/* ---------------- helpers -------------------------------------------------- */
__device__ __forceinline__ unsigned pk2h(float lo, float hi) {
    unsigned u;
    asm("cvt.rn.f16x2.f32 %0, %1, %2;" : "=r"(u) : "f"(hi), "f"(lo));
    return u;
}
__device__ __forceinline__ float sigmoidf_(float x) { return 1.0f / (1.0f + expf(-x)); }

__device__ __forceinline__ void mma16(float c[4], const unsigned a[4], uint2 b) {
    asm volatile(
        "mma.sync.aligned.m16n8k16.row.col.f32.f16.f16.f32 "
        "{%0,%1,%2,%3},{%4,%5,%6,%7},{%8,%9},{%0,%1,%2,%3};"
        : "+f"(c[0]), "+f"(c[1]), "+f"(c[2]), "+f"(c[3])
        : "r"(a[0]), "r"(a[1]), "r"(a[2]), "r"(a[3]), "r"(b.x), "r"(b.y));
}

#define CPA16(d, s) asm volatile("cp.async.ca.shared.global [%0], [%1], 16;" :: "r"(d), "l"(s))
#define CPA_COMMIT() asm volatile("cp.async.commit_group;" ::: "memory")
#define CPA_WAIT0()  asm volatile("cp.async.wait_group 0;" ::: "memory")

__device__ __forceinline__ uint32_t smem_u32(const void* p) {
    uint32_t a;
    asm("{ .reg .u64 t; cvta.to.shared.u64 t, %1; cvt.u32.u64 %0, t; }" : "=r"(a) : "l"(p));
    return a;
}

/* ---------------- small kernels -------------------------------------------- */
__global__ void k_init_proposed() {
    size_t i = (size_t)blockIdx.x * blockDim.x + threadIdx.x;
    size_t n4 = (size_t)NN * HH / 4;
    if (i < n4) ((float4*)g_proposed)[i] = make_float4(0.f, 0.f, 0.f, 0.f);
}
__global__ void k_init_meta() {
    int i = blockIdx.x * blockDim.x + threadIdx.x;
    if (i < TT) { g_tcount[i] = 0; g_tcur[i] = 0; }
    if (i < SORT_CAP) g_sorted[i] = -1;
}
__global__ void k_hist(const int* __restrict__ et) {
    int e = blockIdx.x * blockDim.x + threadIdx.x;
    if (e < EE) atomicAdd(&g_tcount[et[e]], 1);
}
__global__ void k_offsets() {
    if (threadIdx.x == 0 && blockIdx.x == 0) {
        int off = 0;
        for (int t = 0; t < TT; t++) {
            g_toff[t] = off;
            off += ((g_tcount[t] + 127) >> 7) << 7;
        }
        g_toff[TT] = off;
    }
}
__global__ void k_scatter(const int* __restrict__ et) {
    int e = blockIdx.x * blockDim.x + threadIdx.x;
    if (e < EE) {
        int t = et[e];
        int pos = g_toff[t] + atomicAdd(&g_tcur[t], 1);
        g_sorted[pos] = e;
    }
}

/* ---------------- weight prep: fp16 pairs, k-adjacent -----------------------
 * blob row n (64 cols of B^T) x 16 u32; u32 p holds halves (k=2p, k=2p+1).  */
__global__ void k_prep_gru(const float* __restrict__ W0, const float* __restrict__ W1,
                           const float* __restrict__ W2, const float* __restrict__ W3,
                           const float* __restrict__ W4, const float* __restrict__ W5) {
    int kc = blockIdx.x, jb = blockIdx.y, mat = blockIdx.z;
    const float* Ws[6] = {W0, W1, W2, W3, W4, W5};
    const float* W = Ws[mat];
    int tid = threadIdx.x, n = tid & 63, kg = tid >> 6;
    unsigned* dst = &g_wswg[(size_t)((mat * 8 + jb) * 16 + kc) * B_GU32];
#pragma unroll
    for (int p = 0; p < 4; p++) {
        int kk = kg * 8 + p * 2;
        float v0 = W[(size_t)(kc * 32 + kk) * HH + jb * 64 + n];
        float v1 = W[(size_t)(kc * 32 + kk + 1) * HH + jb * 64 + n];
        dst[n * 16 + kg * 4 + p] = pk2h(v0, v1);
    }
}
__global__ void k_prep_edge(const float* __restrict__ W) {
    int kc = blockIdx.x, jb = blockIdx.y;     /* jb 0..47 over 3072 cols */
    int tid = threadIdx.x, n = tid & 63, kg = tid >> 6;
    unsigned* dst = &g_wswe[(size_t)(jb * 16 + kc) * B_GU32];
#pragma unroll
    for (int p = 0; p < 4; p++) {
        int kk = kg * 8 + p * 2;
        float v0 = W[(size_t)(kc * 32 + kk) * (TT * HH) + jb * 64 + n];
        float v1 = W[(size_t)(kc * 32 + kk + 1) * (TT * HH) + jb * 64 + n];
        dst[n * 16 + kg * 4 + p] = pk2h(v0, v1);
    }
}

/* ---------------- fused GRU mma kernel -------------------------------------
 * 512 threads, 16 warps, warp tile 32x16, CTA tile 128x64.
 * A raw fp32 via cp.async; fp16 pack at fragment load (LDS.64 + cvt).       */
__device__ __forceinline__ void gru_fill(uint32_t st, const float* __restrict__ P,
                                         const float* __restrict__ Hm,
                                         int m0, int k0, int jb, int kc, int tid)
{
    /* B: 6 streams x 256 CPA16 = 1536, 3 per thread */
#pragma unroll
    for (int i = 0; i < 3; i++) {
        int gidx = i * 512 + tid;
        int m_ = gidx >> 8, idx = gidx & 255;
        int row = idx >> 2, c = idx & 3;
        const char* src = (const char*)&g_wswg[(size_t)((m_ * 8 + jb) * 16 + kc) * B_GU32];
        CPA16(st + (GRU_BOFF + m_ * B_SU32 + row * BSTR + c * 4) * 4, src + idx * 16);
    }
    /* A: 2 matrices x 128 rows x 8 quads = 2048 CPA16, 4 per thread */
#pragma unroll
    for (int i = 0; i < 4; i++) {
        int idx = i * 512 + tid;
        int mat = idx >> 10, r = (idx >> 3) & 127, q = idx & 7;
        int rg = m0 + r; if (rg > NN - 1) rg = NN - 1;
        const float* s = (mat ? Hm : P) + (size_t)rg * HH + k0 + q * 4;
        CPA16(st + (mat * GRU_A_U32 + r * ASTR + q * 4) * 4, s);
    }
    CPA_COMMIT();
}

__global__ __launch_bounds__(512, 1) void k_gru_mma(
    const float* __restrict__ emb,
    const float* __restrict__ bir, const float* __restrict__ biz,
    const float* __restrict__ bin, const float* __restrict__ bhn,
    float* __restrict__ out)
{
    extern __shared__ unsigned smu[];
    float* bias_s = (float*)smu;                 /* 256 floats */
    unsigned* stage0 = smu + 256;
    uint32_t st0 = smem_u32(stage0);

    int tid = threadIdx.x, lane = tid & 31, warp = tid >> 5;
    int gid = lane >> 2, tig = lane & 3;
    int wm = (warp >> 2) * 32, wn = (warp & 3) * 16;
    int jb = blockIdx.x, m0 = blockIdx.y * 128;

    if (tid < 256) {
        const float* ba[4] = {bir, biz, bin, bhn};
        bias_s[tid] = ba[tid >> 6][jb * 64 + (tid & 63)];
    }

    float accR[2][2][4], accZ[2][2][4], accN[2][2][4], accH[2][2][4];
#pragma unroll
    for (int mf = 0; mf < 2; mf++)
#pragma unroll
        for (int ni = 0; ni < 2; ni++)
#pragma unroll
            for (int q = 0; q < 4; q++) {
                accR[mf][ni][q] = 0.f; accZ[mf][ni][q] = 0.f;
                accN[mf][ni][q] = 0.f; accH[mf][ni][q] = 0.f;
            }

    gru_fill(st0, g_proposed, emb, m0, 0, jb, 0, tid);
    CPA_WAIT0();
    __syncthreads();

    for (int c = 0; c < 16; c++) {
        const unsigned* cur = stage0 + (c & 1) * GRU_STAGE_U32;

        if (c < 15)
            gru_fill(st0 + ((c & 1) ^ 1) * GRU_STAGE_U32 * 4,
                     g_proposed, emb, m0, (c + 1) * 32, jb, c + 1, tid);

        const float* Af = (const float*)cur;
        const unsigned* Bb = cur + GRU_BOFF;
#pragma unroll
        for (int ks = 0; ks < 2; ks++) {
            int ka = ks * 16 + tig * 2;
            unsigned ap[2][4], ah[2][4];
#pragma unroll
            for (int mf = 0; mf < 2; mf++) {
                int r0 = wm + mf * 16 + gid;
                float2 v;
                v = *(const float2*)(Af + r0 * ASTR + ka);
                ap[mf][0] = pk2h(v.x, v.y);
                v = *(const float2*)(Af + (r0 + 8) * ASTR + ka);
                ap[mf][1] = pk2h(v.x, v.y);
                v = *(const float2*)(Af + r0 * ASTR + ka + 8);
                ap[mf][2] = pk2h(v.x, v.y);
                v = *(const float2*)(Af + (r0 + 8) * ASTR + ka + 8);
                ap[mf][3] = pk2h(v.x, v.y);
                v = *(const float2*)(Af + GRU_A_U32 + r0 * ASTR + ka);
                ah[mf][0] = pk2h(v.x, v.y);
                v = *(const float2*)(Af + GRU_A_U32 + (r0 + 8) * ASTR + ka);
                ah[mf][1] = pk2h(v.x, v.y);
                v = *(const float2*)(Af + GRU_A_U32 + r0 * ASTR + ka + 8);
                ah[mf][2] = pk2h(v.x, v.y);
                v = *(const float2*)(Af + GRU_A_U32 + (r0 + 8) * ASTR + ka + 8);
                ah[mf][3] = pk2h(v.x, v.y);
            }
#pragma unroll
            for (int ni = 0; ni < 2; ni++) {
                int cb = (wn + ni * 8 + gid) * BSTR + ks * 8 + tig;
                uint2 b;
                b.x = Bb[0 * B_SU32 + cb]; b.y = Bb[0 * B_SU32 + cb + 4];   /* Wir */
#pragma unroll
                for (int mf = 0; mf < 2; mf++) mma16(accR[mf][ni], ap[mf], b);
                b.x = Bb[1 * B_SU32 + cb]; b.y = Bb[1 * B_SU32 + cb + 4];   /* Whr */
#pragma unroll
                for (int mf = 0; mf < 2; mf++) mma16(accR[mf][ni], ah[mf], b);
                b.x = Bb[2 * B_SU32 + cb]; b.y = Bb[2 * B_SU32 + cb + 4];   /* Wiz */
#pragma unroll
                for (int mf = 0; mf < 2; mf++) mma16(accZ[mf][ni], ap[mf], b);
                b.x = Bb[3 * B_SU32 + cb]; b.y = Bb[3 * B_SU32 + cb + 4];   /* Whz */
#pragma unroll
                for (int mf = 0; mf < 2; mf++) mma16(accZ[mf][ni], ah[mf], b);
                b.x = Bb[4 * B_SU32 + cb]; b.y = Bb[4 * B_SU32 + cb + 4];   /* Win */
#pragma unroll
                for (int mf = 0; mf < 2; mf++) mma16(accN[mf][ni], ap[mf], b);
                b.x = Bb[5 * B_SU32 + cb]; b.y = Bb[5 * B_SU32 + cb + 4];   /* Whn */
#pragma unroll
                for (int mf = 0; mf < 2; mf++) mma16(accH[mf][ni], ah[mf], b);
            }
        }
        CPA_WAIT0();
        __syncthreads();
    }

    /* epilogue: gates */
#pragma unroll
    for (int mf = 0; mf < 2; mf++) {
#pragma unroll
        for (int rp = 0; rp < 2; rp++) {
            int row = m0 + wm + mf * 16 + rp * 8 + gid;
            if (row >= NN) continue;
            const float* hrow = emb + (size_t)row * HH + jb * 64;
            float* orow = out + (size_t)row * HH + jb * 64;
#pragma unroll
            for (int ni = 0; ni < 2; ni++) {
                int c0 = wn + ni * 8 + tig * 2;
                float2 h2 = *(const float2*)(hrow + c0);
                float o[2];
#pragma unroll
                for (int e = 0; e < 2; e++) {
                    int q = rp * 2 + e;
                    int cl = c0 + e;
                    float r = sigmoidf_(accR[mf][ni][q] + bias_s[cl]);
                    float z = sigmoidf_(accZ[mf][ni][q] + bias_s[64 + cl]);
                    float n = tanhf(accN[mf][ni][q] + bias_s[128 + cl]
                                    + r * (accH[mf][ni][q] + bias_s[192 + cl]));
                    float h = e ? h2.y : h2.x;
                    o[e] = (1.f - z) * n + z * h;
                }
                *(float2*)(orow + c0) = make_float2(o[0], o[1]);
            }
        }
    }
}

/* ---------------- edge mma kernel ------------------------------------------
 * 256 threads, 8 warps, warp tile 32x32, CTA tile 128x64.                   */
__device__ __forceinline__ void edge_fill(uint32_t st, const float* __restrict__ emb,
                                          const int* __restrict__ ssrc,
                                          int k0, int jbg, int kc, int tid)
{
    const char* src = (const char*)&g_wswe[(size_t)(jbg * 16 + kc) * B_GU32];
    {
        int row = tid >> 2, c = tid & 3;
        CPA16(st + (GRU_A_U32 + row * BSTR + c * 4) * 4, src + tid * 16);
    }
#pragma unroll
    for (int i = 0; i < 4; i++) {
        int idx = i * 256 + tid, r = idx >> 3, q = idx & 7;
        int nr = ssrc[r]; if (nr < 0) nr = 0;
        CPA16(st + (r * ASTR + q * 4) * 4,
              (const void*)(emb + (size_t)nr * HH + k0 + q * 4));
    }
    CPA_COMMIT();
}

__global__ __launch_bounds__(256, 2) void k_edge_mma(
    const float* __restrict__ emb, const int* __restrict__ src,
    const int* __restrict__ dst, const float* __restrict__ b_edge)
{
    int start = blockIdx.y * 128;
    if (start >= g_toff[TT]) return;
    int t = 0;
#pragma unroll
    for (int i = 1; i < TT; i++) if (start >= g_toff[i]) t = i;
    int jb8 = blockIdx.x;
    int jbg = t * 8 + jb8;

    extern __shared__ unsigned smu[];
    int* s_srow = (int*)smu;             /* 128 */
    int* s_dst  = (int*)smu + 128;       /* 128 */
    float* s_bias = (float*)smu + 256;   /* 64  */
    unsigned* stage0 = smu + 384;
    uint32_t st0 = smem_u32(stage0);

    int tid = threadIdx.x, lane = tid & 31, warp = tid >> 5;
    int gid = lane >> 2, tig = lane & 3;
    int wm = (warp >> 1) * 32, wn = (warp & 1) * 32;

    if (tid < 128) {
        int e = g_sorted[start + tid];
        s_srow[tid] = (e >= 0) ? src[e] : -1;
        s_dst[tid]  = (e >= 0) ? dst[e] : -1;
    }
    if (tid < 64) s_bias[tid] = b_edge[(size_t)t * HH + jb8 * 64 + tid];
    __syncthreads();

    float acc[2][4][4];
#pragma unroll
    for (int mf = 0; mf < 2; mf++)
#pragma unroll
        for (int ni = 0; ni < 4; ni++)
#pragma unroll
            for (int q = 0; q < 4; q++) acc[mf][ni][q] = 0.f;

    edge_fill(st0, emb, s_srow, 0, jbg, 0, tid);
    CPA_WAIT0();
    __syncthreads();

    for (int c = 0; c < 16; c++) {
        const unsigned* cur = stage0 + (c & 1) * EDGE_STAGE_U32;

        if (c < 15)
            edge_fill(st0 + ((c & 1) ^ 1) * EDGE_STAGE_U32 * 4,
                      emb, s_srow, (c + 1) * 32, jbg, c + 1, tid);

        const float* Af = (const float*)cur;
        const unsigned* Bb = cur + GRU_A_U32;
#pragma unroll
        for (int ks = 0; ks < 2; ks++) {
            int ka = ks * 16 + tig * 2;
            unsigned ap[2][4];
#pragma unroll
            for (int mf = 0; mf < 2; mf++) {
                int r0 = wm + mf * 16 + gid;
                float2 v;
                v = *(const float2*)(Af + r0 * ASTR + ka);
                ap[mf][0] = pk2h(v.x, v.y);
                v = *(const float2*)(Af + (r0 + 8) * ASTR + ka);
                ap[mf][1] = pk2h(v.x, v.y);
                v = *(const float2*)(Af + r0 * ASTR + ka + 8);
                ap[mf][2] = pk2h(v.x, v.y);
                v = *(const float2*)(Af + (r0 + 8) * ASTR + ka + 8);
                ap[mf][3] = pk2h(v.x, v.y);
            }
#pragma unroll
            for (int ni = 0; ni < 4; ni++) {
                int cb = (wn + ni * 8 + gid) * BSTR + ks * 8 + tig;
                uint2 b;
                b.x = Bb[cb]; b.y = Bb[cb + 4];
#pragma unroll
                for (int mf = 0; mf < 2; mf++) mma16(acc[mf][ni], ap[mf], b);
            }
        }
        CPA_WAIT0();
        __syncthreads();
    }

    /* epilogue: bias + atomic scatter-add */
#pragma unroll
    for (int mf = 0; mf < 2; mf++) {
#pragma unroll
        for (int rp = 0; rp < 2; rp++) {
            int arow = wm + mf * 16 + rp * 8 + gid;
            int d = s_dst[arow];
            if (d < 0) continue;
            float* prow = g_proposed + (size_t)d * HH + jb8 * 64;
#pragma unroll
            for (int ni = 0; ni < 4; ni++) {
                int c0 = wn + ni * 8 + tig * 2;
                atomicAdd(prow + c0,     acc[mf][ni][rp * 2]     + s_bias[c0]);
                atomicAdd(prow + c0 + 1, acc[mf][ni][rp * 2 + 1] + s_bias[c0 + 1]);
            }
        }
    }
}

/* ---------------- launch --------------------------------------------------- */
extern "C" void kernel_launch(void* const* d_in, const int* in_sizes, int n_in,
                              void* d_out, int out_size)
{
    int s = (n_in >= 18) ? 2 : 0;

    const float* emb    = (const float*)d_in[0];
    const int*   src    = (const int*)d_in[1];
    const int*   dst    = (const int*)d_in[2];
    const int*   et     = (const int*)d_in[3];
    const float* W_edge = (const float*)d_in[4 + s];
    const float* b_edge = (const float*)d_in[5 + s];
    const float* Wir    = (const float*)d_in[6 + s];
    const float* Wiz    = (const float*)d_in[7 + s];
    const float* Win    = (const float*)d_in[8 + s];
    const float* bir    = (const float*)d_in[9 + s];
    const float* biz    = (const float*)d_in[10 + s];
    const float* bin    = (const float*)d_in[11 + s];
    const float* Whr    = (const float*)d_in[12 + s];
    const float* Whz    = (const float*)d_in[13 + s];
    const float* Whn    = (const float*)d_in[14 + s];
    const float* bhn    = (const float*)d_in[15 + s];
    float* out = (float*)d_out;

    static int attr_done = 0;
    if (!attr_done) {
        cudaFuncSetAttribute(k_gru_mma,  cudaFuncAttributeMaxDynamicSharedMemorySize, GRU_SMEM);
        cudaFuncSetAttribute(k_edge_mma, cudaFuncAttributeMaxDynamicSharedMemorySize, EDGE_SMEM);
        attr_done = 1;
    }

    k_init_proposed<<<(NN * HH / 4 + 255) / 256, 256>>>();
    k_init_meta<<<(SORT_CAP + 255) / 256, 256>>>();
    k_hist<<<(EE + 255) / 256, 256>>>(et);
    k_offsets<<<1, 32>>>();
    k_scatter<<<(EE + 255) / 256, 256>>>(et);

    k_prep_gru<<<dim3(16, 8, 6), 256>>>(Wir, Whr, Wiz, Whz, Win, Whn);
    k_prep_edge<<<dim3(16, 48), 256>>>(W_edge);

    k_edge_mma<<<dim3(8, EGRP), 256, EDGE_SMEM>>>(emb, src, dst, b_edge);
    k_gru_mma<<<dim3(8, MBLK), 512, GRU_SMEM>>>(emb, bir, biz, bin, bhn, out);
}

// round 8
// speedup vs baseline: 4.2381x; 1.0265x over previous
#include <cuda_runtime.h>
#include <cuda_fp16.h>
#include <cstdint>
#include <math.h>

#define NN 50000
#define EE 100000
#define HH 512
#define TT 6
#define MBLK 391                       /* ceil(NN/128) */
#define EGRP 788                       /* ceil((EE + TT*128)/128) */
#define SORT_CAP (EE + TT * 128)

#define RSTR 24                        /* u32 stride per 32-k fp16 row in smem */
#define B_GU32 (64 * 16)               /* global B blob chunk: 64 rows x 16 u32 */

#define A_U32H   (128 * RSTR)                           /* 3072 */
#define B_U32H   (64 * RSTR)                            /* 1536 */
#define GRU_BOFFH (2 * A_U32H)                          /* 6144 */
#define GRU_STAGE_U32 (GRU_BOFFH + 6 * B_U32H)          /* 15360 */
#define GRU_SMEMH (1024 + 3 * GRU_STAGE_U32 * 4)        /* 185344 B */

#define EDGE_STAGE_U32 (A_U32H + B_U32H)                /* 4608 */
#define EDGE_SMEMH (1536 + 3 * EDGE_STAGE_U32 * 4)      /* 56832 B */

/* ---------------- static device scratch ----------------------------------- */
__device__ float    g_proposed[(size_t)NN * HH];
__device__ unsigned g_emb16[(size_t)NN * 256];    /* fp16 interleaved, 256 u32/row */
__device__ unsigned g_prop16[(size_t)NN * 256];   /* fp16 interleaved, 256 u32/row */
__device__ unsigned g_wswg[(size_t)6 * 8 * 16 * B_GU32];
__device__ unsigned g_wswe[(size_t)48 * 16 * B_GU32];
__device__ int g_sorted[SORT_CAP];
__device__ int g_tcount[TT];
__device__ int g_tcur[TT];
__device__ int g_toff[TT + 1];

/* ---------------- helpers -------------------------------------------------- */
__device__ __forceinline__ unsigned pk2h(float lo, float hi) {
    unsigned u;
    asm("cvt.rn.f16x2.f32 %0, %1, %2;" : "=r"(u) : "f"(hi), "f"(lo));
    return u;
}
__device__ __forceinline__ float sigmoidf_(float x) { return 1.0f / (1.0f + expf(-x)); }

__device__ __forceinline__ void mma16(float c[4], const unsigned a[4], uint2 b) {
    asm volatile(
        "mma.sync.aligned.m16n8k16.row.col.f32.f16.f16.f32 "
        "{%0,%1,%2,%3},{%4,%5,%6,%7},{%8,%9},{%0,%1,%2,%3};"
        : "+f"(c[0]), "+f"(c[1]), "+f"(c[2]), "+f"(c[3])
        : "r"(a[0]), "r"(a[1]), "r"(a[2]), "r"(a[3]), "r"(b.x), "r"(b.y));
}

#define CPA16(d, s) asm volatile("cp.async.ca.shared.global [%0], [%1], 16;" :: "r"(d), "l"(s))
#define CPA_COMMIT() asm volatile("cp.async.commit_group;" ::: "memory")
#define CPA_WAIT0()  asm volatile("cp.async.wait_group 0;" ::: "memory")
#define CPA_WAIT1()  asm volatile("cp.async.wait_group 1;" ::: "memory")

__device__ __forceinline__ uint32_t smem_u32(const void* p) {
    uint32_t a;
    asm("{ .reg .u64 t; cvta.to.shared.u64 t, %1; cvt.u32.u64 %0, t; }" : "=r"(a) : "l"(p));
    return a;
}

/* ---------------- small kernels -------------------------------------------- */
__global__ void k_init_proposed() {
    size_t i = (size_t)blockIdx.x * blockDim.x + threadIdx.x;
    size_t n4 = (size_t)NN * HH / 4;
    if (i < n4) ((float4*)g_proposed)[i] = make_float4(0.f, 0.f, 0.f, 0.f);
}
__global__ void k_init_meta() {
    int i = blockIdx.x * blockDim.x + threadIdx.x;
    if (i < TT) { g_tcount[i] = 0; g_tcur[i] = 0; }
    if (i < SORT_CAP) g_sorted[i] = -1;
}
__global__ void k_hist(const int* __restrict__ et) {
    int e = blockIdx.x * blockDim.x + threadIdx.x;
    if (e < EE) atomicAdd(&g_tcount[et[e]], 1);
}
__global__ void k_offsets() {
    if (threadIdx.x == 0 && blockIdx.x == 0) {
        int off = 0;
        for (int t = 0; t < TT; t++) {
            g_toff[t] = off;
            off += ((g_tcount[t] + 127) >> 7) << 7;
        }
        g_toff[TT] = off;
    }
}
__global__ void k_scatter(const int* __restrict__ et) {
    int e = blockIdx.x * blockDim.x + threadIdx.x;
    if (e < EE) {
        int t = et[e];
        int pos = g_toff[t] + atomicAdd(&g_tcur[t], 1);
        g_sorted[pos] = e;
    }
}

/* ---------------- fp32 -> interleaved fp16 conversion -----------------------
 * Each thread converts one 16-float group into 8 u32; kpair j -> slot
 * 2*(j&3)+(j>>2), so LDS.64 at slot 2t gives kpairs (t, t+4).              */
__global__ void k_cvt16(const float* __restrict__ src, unsigned* __restrict__ dst) {
    size_t i = (size_t)blockIdx.x * blockDim.x + threadIdx.x;
    if (i >= (size_t)NN * 32) return;
    const float4* s4 = (const float4*)(src + i * 16);
    float4 f0 = s4[0], f1 = s4[1], f2 = s4[2], f3 = s4[3];
    unsigned o[8];
    o[0] = pk2h(f0.x, f0.y); o[2] = pk2h(f0.z, f0.w);
    o[4] = pk2h(f1.x, f1.y); o[6] = pk2h(f1.z, f1.w);
    o[1] = pk2h(f2.x, f2.y); o[3] = pk2h(f2.z, f2.w);
    o[5] = pk2h(f3.x, f3.y); o[7] = pk2h(f3.z, f3.w);
    uint4* d4 = (uint4*)(dst + i * 8);
    d4[0] = make_uint4(o[0], o[1], o[2], o[3]);
    d4[1] = make_uint4(o[4], o[5], o[6], o[7]);
}

/* ---------------- weight prep: fp16 interleaved blobs ---------------------- */
__global__ void k_prep_gru(const float* __restrict__ W0, const float* __restrict__ W1,
                           const float* __restrict__ W2, const float* __restrict__ W3,
                           const float* __restrict__ W4, const float* __restrict__ W5) {
    int kc = blockIdx.x, jb = blockIdx.y, mat = blockIdx.z;
    const float* Ws[6] = {W0, W1, W2, W3, W4, W5};
    const float* W = Ws[mat];
    int tid = threadIdx.x, n = tid & 63, kg = tid >> 6;
    unsigned* dst = &g_wswg[(size_t)((mat * 8 + jb) * 16 + kc) * B_GU32];
#pragma unroll
    for (int p = 0; p < 4; p++) {
        int jp = kg * 4 + p;                 /* kpair index within 32-k chunk */
        int kk = kc * 32 + jp * 2;
        float v0 = W[(size_t)kk * HH + jb * 64 + n];
        float v1 = W[(size_t)(kk + 1) * HH + jb * 64 + n];
        int g = jp >> 3, jj = jp & 7;
        dst[n * 16 + g * 8 + 2 * (jj & 3) + (jj >> 2)] = pk2h(v0, v1);
    }
}
__global__ void k_prep_edge(const float* __restrict__ W) {
    int kc = blockIdx.x, jb = blockIdx.y;
    int tid = threadIdx.x, n = tid & 63, kg = tid >> 6;
    unsigned* dst = &g_wswe[(size_t)(jb * 16 + kc) * B_GU32];
#pragma unroll
    for (int p = 0; p < 4; p++) {
        int jp = kg * 4 + p;
        int kk = kc * 32 + jp * 2;
        float v0 = W[(size_t)kk * (TT * HH) + jb * 64 + n];
        float v1 = W[(size_t)(kk + 1) * (TT * HH) + jb * 64 + n];
        int g = jp >> 3, jj = jp & 7;
        dst[n * 16 + g * 8 + 2 * (jj & 3) + (jj >> 2)] = pk2h(v0, v1);
    }
}

/* ---------------- fused GRU mma kernel -------------------------------------
 * 512 threads, 16 warps, warp tile 32x16, CTA tile 128x64. 3-stage pipe.    */
__device__ __forceinline__ void gru_fill(uint32_t st, int m0, int jb, int kc, int tid)
{
#pragma unroll
    for (int i = 0; i < 2; i++) {             /* A: 1024 CPA16 */
        int idx = i * 512 + tid;
        int mat = idx >> 9, rq = idx & 511, r = rq >> 2, q = rq & 3;
        int rg = m0 + r; if (rg > NN - 1) rg = NN - 1;
        const unsigned* s = (mat ? g_emb16 : g_prop16) + (size_t)rg * 256 + kc * 16 + q * 4;
        CPA16(st + (mat * A_U32H + r * RSTR + q * 4) * 4, (const void*)s);
    }
#pragma unroll
    for (int i = 0; i < 3; i++) {             /* B: 1536 CPA16 */
        int gidx = i * 512 + tid;
        int m_ = gidx >> 8, idx = gidx & 255, row = idx >> 2, c = idx & 3;
        const char* src = (const char*)&g_wswg[(size_t)((m_ * 8 + jb) * 16 + kc) * B_GU32];
        CPA16(st + (GRU_BOFFH + m_ * B_U32H + row * RSTR + c * 4) * 4, src + idx * 16);
    }
    CPA_COMMIT();
}

__global__ __launch_bounds__(512, 1) void k_gru_mma(
    const float* __restrict__ emb,
    const float* __restrict__ bir, const float* __restrict__ biz,
    const float* __restrict__ bin, const float* __restrict__ bhn,
    float* __restrict__ out)
{
    extern __shared__ unsigned smu[];
    float* bias_s = (float*)smu;                 /* 256 floats */
    unsigned* stage0 = smu + 256;
    uint32_t st0 = smem_u32(stage0);

    int tid = threadIdx.x, lane = tid & 31, warp = tid >> 5;
    int gid = lane >> 2, tig = lane & 3;
    int wm = (warp >> 2) * 32, wn = (warp & 3) * 16;
    int jb = blockIdx.x, m0 = blockIdx.y * 128;

    if (tid < 256) {
        const float* ba[4] = {bir, biz, bin, bhn};
        bias_s[tid] = ba[tid >> 6][jb * 64 + (tid & 63)];
    }

    float accR[2][2][4], accZ[2][2][4], accN[2][2][4], accH[2][2][4];
#pragma unroll
    for (int mf = 0; mf < 2; mf++)
#pragma unroll
        for (int ni = 0; ni < 2; ni++)
#pragma unroll
            for (int q = 0; q < 4; q++) {
                accR[mf][ni][q] = 0.f; accZ[mf][ni][q] = 0.f;
                accN[mf][ni][q] = 0.f; accH[mf][ni][q] = 0.f;
            }

    gru_fill(st0, m0, jb, 0, tid);
    gru_fill(st0 + GRU_STAGE_U32 * 4, m0, jb, 1, tid);

    for (int c = 0; c < 16; c++) {
        if (c < 15) CPA_WAIT1(); else CPA_WAIT0();
        __syncthreads();
        if (c + 2 < 16)
            gru_fill(st0 + ((c + 2) % 3) * GRU_STAGE_U32 * 4, m0, jb, c + 2, tid);

        const unsigned* cur = stage0 + (c % 3) * GRU_STAGE_U32;
        const unsigned* Ap = cur;
        const unsigned* Ah = cur + A_U32H;
        const unsigned* Bb = cur + GRU_BOFFH;
#pragma unroll
        for (int ks = 0; ks < 2; ks++) {
            int ko = ks * 8 + tig * 2;
            unsigned ap[2][4], ah[2][4];
#pragma unroll
            for (int mf = 0; mf < 2; mf++) {
                int r0 = wm + mf * 16 + gid;
                uint2 v0 = *(const uint2*)(Ap + r0 * RSTR + ko);
                uint2 v1 = *(const uint2*)(Ap + (r0 + 8) * RSTR + ko);
                ap[mf][0] = v0.x; ap[mf][1] = v1.x; ap[mf][2] = v0.y; ap[mf][3] = v1.y;
                uint2 w0 = *(const uint2*)(Ah + r0 * RSTR + ko);
                uint2 w1 = *(const uint2*)(Ah + (r0 + 8) * RSTR + ko);
                ah[mf][0] = w0.x; ah[mf][1] = w1.x; ah[mf][2] = w0.y; ah[mf][3] = w1.y;
            }
#pragma unroll
            for (int ni = 0; ni < 2; ni++) {
                int cb = (wn + ni * 8 + gid) * RSTR + ko;
                uint2 b;
                b = *(const uint2*)(Bb + 0 * B_U32H + cb);   /* Wir */
#pragma unroll
                for (int mf = 0; mf < 2; mf++) mma16(accR[mf][ni], ap[mf], b);
                b = *(const uint2*)(Bb + 1 * B_U32H + cb);   /* Whr */
#pragma unroll
                for (int mf = 0; mf < 2; mf++) mma16(accR[mf][ni], ah[mf], b);
                b = *(const uint2*)(Bb + 2 * B_U32H + cb);   /* Wiz */
#pragma unroll
                for (int mf = 0; mf < 2; mf++) mma16(accZ[mf][ni], ap[mf], b);
                b = *(const uint2*)(Bb + 3 * B_U32H + cb);   /* Whz */
#pragma unroll
                for (int mf = 0; mf < 2; mf++) mma16(accZ[mf][ni], ah[mf], b);
                b = *(const uint2*)(Bb + 4 * B_U32H + cb);   /* Win */
#pragma unroll
                for (int mf = 0; mf < 2; mf++) mma16(accN[mf][ni], ap[mf], b);
                b = *(const uint2*)(Bb + 5 * B_U32H + cb);   /* Whn */
#pragma unroll
                for (int mf = 0; mf < 2; mf++) mma16(accH[mf][ni], ah[mf], b);
            }
        }
    }

    /* epilogue: gates (h read in fp32) */
#pragma unroll
    for (int mf = 0; mf < 2; mf++) {
#pragma unroll
        for (int rp = 0; rp < 2; rp++) {
            int row = m0 + wm + mf * 16 + rp * 8 + gid;
            if (row >= NN) continue;
            const float* hrow = emb + (size_t)row * HH + jb * 64;
            float* orow = out + (size_t)row * HH + jb * 64;
#pragma unroll
            for (int ni = 0; ni < 2; ni++) {
                int c0 = wn + ni * 8 + tig * 2;
                float2 h2 = *(const float2*)(hrow + c0);
                float o[2];
#pragma unroll
                for (int e = 0; e < 2; e++) {
                    int q = rp * 2 + e;
                    int cl = c0 + e;
                    float r = sigmoidf_(accR[mf][ni][q] + bias_s[cl]);
                    float z = sigmoidf_(accZ[mf][ni][q] + bias_s[64 + cl]);
                    float n = tanhf(accN[mf][ni][q] + bias_s[128 + cl]
                                    + r * (accH[mf][ni][q] + bias_s[192 + cl]));
                    float h = e ? h2.y : h2.x;
                    o[e] = (1.f - z) * n + z * h;
                }
                *(float2*)(orow + c0) = make_float2(o[0], o[1]);
            }
        }
    }
}

/* ---------------- edge mma kernel ------------------------------------------
 * 256 threads, 8 warps, warp tile 32x32, CTA tile 128x64. 3-stage pipe.     */
__device__ __forceinline__ void edge_fill(uint32_t st, const int* __restrict__ ssrc,
                                          int jbg, int kc, int tid)
{
#pragma unroll
    for (int i = 0; i < 2; i++) {             /* A: 512 CPA16 */
        int idx = i * 256 + tid, r = idx >> 2, q = idx & 3;
        int nr = ssrc[r]; if (nr < 0) nr = 0;
        const unsigned* s = g_emb16 + (size_t)nr * 256 + kc * 16 + q * 4;
        CPA16(st + (r * RSTR + q * 4) * 4, (const void*)s);
    }
    {                                          /* B: 256 CPA16 */
        int row = tid >> 2, c = tid & 3;
        const char* src = (const char*)&g_wswe[(size_t)(jbg * 16 + kc) * B_GU32];
        CPA16(st + (A_U32H + row * RSTR + c * 4) * 4, src + tid * 16);
    }
    CPA_COMMIT();
}

__global__ __launch_bounds__(256, 2) void k_edge_mma(
    const int* __restrict__ src, const int* __restrict__ dst,
    const float* __restrict__ b_edge)
{
    int start = blockIdx.y * 128;
    if (start >= g_toff[TT]) return;
    int t = 0;
#pragma unroll
    for (int i = 1; i < TT; i++) if (start >= g_toff[i]) t = i;
    int jb8 = blockIdx.x;
    int jbg = t * 8 + jb8;

    extern __shared__ unsigned smu[];
    int* s_srow = (int*)smu;             /* 128 */
    int* s_dst  = (int*)smu + 128;       /* 128 */
    float* s_bias = (float*)smu + 256;   /* 64  */
    unsigned* stage0 = smu + 384;
    uint32_t st0 = smem_u32(stage0);

    int tid = threadIdx.x, lane = tid & 31, warp = tid >> 5;
    int gid = lane >> 2, tig = lane & 3;
    int wm = (warp >> 1) * 32, wn = (warp & 1) * 32;

    if (tid < 128) {
        int e = g_sorted[start + tid];
        s_srow[tid] = (e >= 0) ? src[e] : -1;
        s_dst[tid]  = (e >= 0) ? dst[e] : -1;
    }
    if (tid < 64) s_bias[tid] = b_edge[(size_t)t * HH + jb8 * 64 + tid];
    __syncthreads();

    float acc[2][4][4];
#pragma unroll
    for (int mf = 0; mf < 2; mf++)
#pragma unroll
        for (int ni = 0; ni < 4; ni++)
#pragma unroll
            for (int q = 0; q < 4; q++) acc[mf][ni][q] = 0.f;

    edge_fill(st0, s_srow, jbg, 0, tid);
    edge_fill(st0 + EDGE_STAGE_U32 * 4, s_srow, jbg, 1, tid);

    for (int c = 0; c < 16; c++) {
        if (c < 15) CPA_WAIT1(); else CPA_WAIT0();
        __syncthreads();
        if (c + 2 < 16)
            edge_fill(st0 + ((c + 2) % 3) * EDGE_STAGE_U32 * 4, s_srow, jbg, c + 2, tid);

        const unsigned* cur = stage0 + (c % 3) * EDGE_STAGE_U32;
        const unsigned* Ap = cur;
        const unsigned* Bb = cur + A_U32H;
#pragma unroll
        for (int ks = 0; ks < 2; ks++) {
            int ko = ks * 8 + tig * 2;
            unsigned ap[2][4];
#pragma unroll
            for (int mf = 0; mf < 2; mf++) {
                int r0 = wm + mf * 16 + gid;
                uint2 v0 = *(const uint2*)(Ap + r0 * RSTR + ko);
                uint2 v1 = *(const uint2*)(Ap + (r0 + 8) * RSTR + ko);
                ap[mf][0] = v0.x; ap[mf][1] = v1.x; ap[mf][2] = v0.y; ap[mf][3] = v1.y;
            }
#pragma unroll
            for (int ni = 0; ni < 4; ni++) {
                uint2 b = *(const uint2*)(Bb + (wn + ni * 8 + gid) * RSTR + ko);
#pragma unroll
                for (int mf = 0; mf < 2; mf++) mma16(acc[mf][ni], ap[mf], b);
            }
        }
    }

    /* epilogue: bias + atomic scatter-add */
#pragma unroll
    for (int mf = 0; mf < 2; mf++) {
#pragma unroll
        for (int rp = 0; rp < 2; rp++) {
            int arow = wm + mf * 16 + rp * 8 + gid;
            int d = s_dst[arow];
            if (d < 0) continue;
            float* prow = g_proposed + (size_t)d * HH + jb8 * 64;
#pragma unroll
            for (int ni = 0; ni < 4; ni++) {
                int c0 = wn + ni * 8 + tig * 2;
                atomicAdd(prow + c0,     acc[mf][ni][rp * 2]     + s_bias[c0]);
                atomicAdd(prow + c0 + 1, acc[mf][ni][rp * 2 + 1] + s_bias[c0 + 1]);
            }
        }
    }
}

/* ---------------- launch --------------------------------------------------- */
extern "C" void kernel_launch(void* const* d_in, const int* in_sizes, int n_in,
                              void* d_out, int out_size)
{
    int s = (n_in >= 18) ? 2 : 0;

    const float* emb    = (const float*)d_in[0];
    const int*   src    = (const int*)d_in[1];
    const int*   dst    = (const int*)d_in[2];
    const int*   et     = (const int*)d_in[3];
    const float* W_edge = (const float*)d_in[4 + s];
    const float* b_edge = (const float*)d_in[5 + s];
    const float* Wir    = (const float*)d_in[6 + s];
    const float* Wiz    = (const float*)d_in[7 + s];
    const float* Win    = (const float*)d_in[8 + s];
    const float* bir    = (const float*)d_in[9 + s];
    const float* biz    = (const float*)d_in[10 + s];
    const float* bin    = (const float*)d_in[11 + s];
    const float* Whr    = (const float*)d_in[12 + s];
    const float* Whz    = (const float*)d_in[13 + s];
    const float* Whn    = (const float*)d_in[14 + s];
    const float* bhn    = (const float*)d_in[15 + s];
    float* out = (float*)d_out;

    float* d_prop;    cudaGetSymbolAddress((void**)&d_prop, g_proposed);
    unsigned* d_e16;  cudaGetSymbolAddress((void**)&d_e16, g_emb16);
    unsigned* d_p16;  cudaGetSymbolAddress((void**)&d_p16, g_prop16);

    static int attr_done = 0;
    if (!attr_done) {
        cudaFuncSetAttribute(k_gru_mma,  cudaFuncAttributeMaxDynamicSharedMemorySize, GRU_SMEMH);
        cudaFuncSetAttribute(k_edge_mma, cudaFuncAttributeMaxDynamicSharedMemorySize, EDGE_SMEMH);
        attr_done = 1;
    }

    k_init_proposed<<<(NN * HH / 4 + 255) / 256, 256>>>();
    k_init_meta<<<(SORT_CAP + 255) / 256, 256>>>();
    k_hist<<<(EE + 255) / 256, 256>>>(et);
    k_offsets<<<1, 32>>>();
    k_scatter<<<(EE + 255) / 256, 256>>>(et);

    k_prep_gru<<<dim3(16, 8, 6), 256>>>(Wir, Whr, Wiz, Whz, Win, Whn);
    k_prep_edge<<<dim3(16, 48), 256>>>(W_edge);
    k_cvt16<<<(NN * 32 + 255) / 256, 256>>>(emb, d_e16);

    k_edge_mma<<<dim3(8, EGRP), 256, EDGE_SMEMH>>>(src, dst, b_edge);

    k_cvt16<<<(NN * 32 + 255) / 256, 256>>>(d_prop, d_p16);
    k_gru_mma<<<dim3(8, MBLK), 512, GRU_SMEMH>>>(emb, bir, biz, bin, bhn, out);
}

// round 9
// speedup vs baseline: 4.3519x; 1.0269x over previous
#include <cuda_runtime.h>
#include <cuda_fp16.h>
#include <cstdint>
#include <math.h>

#define NN 50000
#define EE 100000
#define HH 512
#define TT 6
#define MBLK 391                       /* ceil(NN/128) */
#define EGRP 788                       /* ceil((EE + TT*128)/128) */
#define SORT_CAP (EE + TT * 128)

#define RSTR 24                        /* u32 stride per 32-k fp16 row in smem */
#define B_GU32 (64 * 16)               /* global B blob chunk: 64 rows x 16 u32 */

#define A_U32H   (128 * RSTR)                           /* 3072 */
#define B_U32H   (64 * RSTR)                            /* 1536 */
#define GRU_BOFFH (2 * A_U32H)                          /* 6144 */
#define GRU_STAGE_U32 (GRU_BOFFH + 6 * B_U32H)          /* 15360 */
#define GRU_SMEMH (1024 + 3 * GRU_STAGE_U32 * 4)        /* 185344 B */

#define EDGE_STAGE_U32 (A_U32H + B_U32H)                /* 4608 */
#define EDGE_SMEMH (1536 + 3 * EDGE_STAGE_U32 * 4)      /* 56832 B */

/* ---------------- static device scratch ----------------------------------- */
__device__ float    g_proposed[(size_t)NN * HH];
__device__ unsigned g_emb16[(size_t)NN * 256];    /* fp16 interleaved, 256 u32/row */
__device__ unsigned g_prop16[(size_t)NN * 256];   /* fp16 interleaved, 256 u32/row */
__device__ unsigned g_wswg[(size_t)6 * 8 * 16 * B_GU32];
__device__ unsigned g_wswe[(size_t)48 * 16 * B_GU32];
__device__ int g_sorted[SORT_CAP];
__device__ int g_tcount[TT];
__device__ int g_tcur[TT];
__device__ int g_toff[TT + 1];

/* ---------------- helpers -------------------------------------------------- */
__device__ __forceinline__ unsigned pk2h(float lo, float hi) {
    unsigned u;
    asm("cvt.rn.f16x2.f32 %0, %1, %2;" : "=r"(u) : "f"(hi), "f"(lo));
    return u;
}
__device__ __forceinline__ float sigmoidf_(float x) { return 1.0f / (1.0f + expf(-x)); }

__device__ __forceinline__ void mma16(float c[4], const unsigned a[4], uint2 b) {
    asm volatile(
        "mma.sync.aligned.m16n8k16.row.col.f32.f16.f16.f32 "
        "{%0,%1,%2,%3},{%4,%5,%6,%7},{%8,%9},{%0,%1,%2,%3};"
        : "+f"(c[0]), "+f"(c[1]), "+f"(c[2]), "+f"(c[3])
        : "r"(a[0]), "r"(a[1]), "r"(a[2]), "r"(a[3]), "r"(b.x), "r"(b.y));
}

__device__ __forceinline__ void red2(float* p, float v0, float v1) {
    asm volatile("red.global.add.v2.f32 [%0], {%1, %2};"
                 :: "l"(p), "f"(v0), "f"(v1) : "memory");
}

#define CPA16(d, s) asm volatile("cp.async.ca.shared.global [%0], [%1], 16;" :: "r"(d), "l"(s))
#define CPA_COMMIT() asm volatile("cp.async.commit_group;" ::: "memory")
#define CPA_WAIT0()  asm volatile("cp.async.wait_group 0;" ::: "memory")
#define CPA_WAIT1()  asm volatile("cp.async.wait_group 1;" ::: "memory")

__device__ __forceinline__ uint32_t smem_u32(const void* p) {
    uint32_t a;
    asm("{ .reg .u64 t; cvta.to.shared.u64 t, %1; cvt.u32.u64 %0, t; }" : "=r"(a) : "l"(p));
    return a;
}

/* ---------------- small kernels -------------------------------------------- */
__global__ void k_init_proposed() {
    size_t i = (size_t)blockIdx.x * blockDim.x + threadIdx.x;
    size_t n4 = (size_t)NN * HH / 4;
    if (i < n4) ((float4*)g_proposed)[i] = make_float4(0.f, 0.f, 0.f, 0.f);
}
__global__ void k_init_meta() {
    int i = blockIdx.x * blockDim.x + threadIdx.x;
    if (i < TT) { g_tcount[i] = 0; g_tcur[i] = 0; }
    if (i < SORT_CAP) g_sorted[i] = -1;
}
__global__ void k_hist(const int* __restrict__ et) {
    int e = blockIdx.x * blockDim.x + threadIdx.x;
    if (e < EE) atomicAdd(&g_tcount[et[e]], 1);
}
__global__ void k_offsets() {
    if (threadIdx.x == 0 && blockIdx.x == 0) {
        int off = 0;
        for (int t = 0; t < TT; t++) {
            g_toff[t] = off;
            off += ((g_tcount[t] + 127) >> 7) << 7;
        }
        g_toff[TT] = off;
    }
}
__global__ void k_scatter(const int* __restrict__ et) {
    int e = blockIdx.x * blockDim.x + threadIdx.x;
    if (e < EE) {
        int t = et[e];
        int pos = g_toff[t] + atomicAdd(&g_tcur[t], 1);
        g_sorted[pos] = e;
    }
}

/* ---------------- fp32 -> interleaved fp16 conversion -----------------------
 * Each thread converts one 16-float group into 8 u32; kpair j -> slot
 * 2*(j&3)+(j>>2), so LDS.64 at slot 2t gives kpairs (t, t+4).              */
__global__ void k_cvt16(const float* __restrict__ src, unsigned* __restrict__ dst) {
    size_t i = (size_t)blockIdx.x * blockDim.x + threadIdx.x;
    if (i >= (size_t)NN * 32) return;
    const float4* s4 = (const float4*)(src + i * 16);
    float4 f0 = s4[0], f1 = s4[1], f2 = s4[2], f3 = s4[3];
    unsigned o[8];
    o[0] = pk2h(f0.x, f0.y); o[2] = pk2h(f0.z, f0.w);
    o[4] = pk2h(f1.x, f1.y); o[6] = pk2h(f1.z, f1.w);
    o[1] = pk2h(f2.x, f2.y); o[3] = pk2h(f2.z, f2.w);
    o[5] = pk2h(f3.x, f3.y); o[7] = pk2h(f3.z, f3.w);
    uint4* d4 = (uint4*)(dst + i * 8);
    d4[0] = make_uint4(o[0], o[1], o[2], o[3]);
    d4[1] = make_uint4(o[4], o[5], o[6], o[7]);
}

/* ---------------- weight prep: fp16 interleaved blobs ---------------------- */
__global__ void k_prep_gru(const float* __restrict__ W0, const float* __restrict__ W1,
                           const float* __restrict__ W2, const float* __restrict__ W3,
                           const float* __restrict__ W4, const float* __restrict__ W5) {
    int kc = blockIdx.x, jb = blockIdx.y, mat = blockIdx.z;
    const float* Ws[6] = {W0, W1, W2, W3, W4, W5};
    const float* W = Ws[mat];
    int tid = threadIdx.x, n = tid & 63, kg = tid >> 6;
    unsigned* dst = &g_wswg[(size_t)((mat * 8 + jb) * 16 + kc) * B_GU32];
#pragma unroll
    for (int p = 0; p < 4; p++) {
        int jp = kg * 4 + p;                 /* kpair index within 32-k chunk */
        int kk = kc * 32 + jp * 2;
        float v0 = W[(size_t)kk * HH + jb * 64 + n];
        float v1 = W[(size_t)(kk + 1) * HH + jb * 64 + n];
        int g = jp >> 3, jj = jp & 7;
        dst[n * 16 + g * 8 + 2 * (jj & 3) + (jj >> 2)] = pk2h(v0, v1);
    }
}
__global__ void k_prep_edge(const float* __restrict__ W) {
    int kc = blockIdx.x, jb = blockIdx.y;
    int tid = threadIdx.x, n = tid & 63, kg = tid >> 6;
    unsigned* dst = &g_wswe[(size_t)(jb * 16 + kc) * B_GU32];
#pragma unroll
    for (int p = 0; p < 4; p++) {
        int jp = kg * 4 + p;
        int kk = kc * 32 + jp * 2;
        float v0 = W[(size_t)kk * (TT * HH) + jb * 64 + n];
        float v1 = W[(size_t)(kk + 1) * (TT * HH) + jb * 64 + n];
        int g = jp >> 3, jj = jp & 7;
        dst[n * 16 + g * 8 + 2 * (jj & 3) + (jj >> 2)] = pk2h(v0, v1);
    }
}

/* ---------------- fused GRU mma kernel -------------------------------------
 * 512 threads, 16 warps, warp tile 32x16, CTA tile 128x64. 3-stage pipe.    */
__device__ __forceinline__ void gru_fill(uint32_t st, int m0, int jb, int kc, int tid)
{
#pragma unroll
    for (int i = 0; i < 2; i++) {             /* A: 1024 CPA16 */
        int idx = i * 512 + tid;
        int mat = idx >> 9, rq = idx & 511, r = rq >> 2, q = rq & 3;
        int rg = m0 + r; if (rg > NN - 1) rg = NN - 1;
        const unsigned* s = (mat ? g_emb16 : g_prop16) + (size_t)rg * 256 + kc * 16 + q * 4;
        CPA16(st + (mat * A_U32H + r * RSTR + q * 4) * 4, (const void*)s);
    }
#pragma unroll
    for (int i = 0; i < 3; i++) {             /* B: 1536 CPA16 */
        int gidx = i * 512 + tid;
        int m_ = gidx >> 8, idx = gidx & 255, row = idx >> 2, c = idx & 3;
        const char* src = (const char*)&g_wswg[(size_t)((m_ * 8 + jb) * 16 + kc) * B_GU32];
        CPA16(st + (GRU_BOFFH + m_ * B_U32H + row * RSTR + c * 4) * 4, src + idx * 16);
    }
    CPA_COMMIT();
}

__global__ __launch_bounds__(512, 1) void k_gru_mma(
    const float* __restrict__ emb,
    const float* __restrict__ bir, const float* __restrict__ biz,
    const float* __restrict__ bin, const float* __restrict__ bhn,
    float* __restrict__ out)
{
    extern __shared__ unsigned smu[];
    float* bias_s = (float*)smu;                 /* 256 floats */
    unsigned* stage0 = smu + 256;
    uint32_t st0 = smem_u32(stage0);

    int tid = threadIdx.x, lane = tid & 31, warp = tid >> 5;
    int gid = lane >> 2, tig = lane & 3;
    int wm = (warp >> 2) * 32, wn = (warp & 3) * 16;
    int jb = blockIdx.x, m0 = blockIdx.y * 128;

    if (tid < 256) {
        const float* ba[4] = {bir, biz, bin, bhn};
        bias_s[tid] = ba[tid >> 6][jb * 64 + (tid & 63)];
    }

    float accR[2][2][4], accZ[2][2][4], accN[2][2][4], accH[2][2][4];
#pragma unroll
    for (int mf = 0; mf < 2; mf++)
#pragma unroll
        for (int ni = 0; ni < 2; ni++)
#pragma unroll
            for (int q = 0; q < 4; q++) {
                accR[mf][ni][q] = 0.f; accZ[mf][ni][q] = 0.f;
                accN[mf][ni][q] = 0.f; accH[mf][ni][q] = 0.f;
            }

    gru_fill(st0, m0, jb, 0, tid);
    gru_fill(st0 + GRU_STAGE_U32 * 4, m0, jb, 1, tid);

    for (int c = 0; c < 16; c++) {
        if (c < 15) CPA_WAIT1(); else CPA_WAIT0();
        __syncthreads();
        if (c + 2 < 16)
            gru_fill(st0 + ((c + 2) % 3) * GRU_STAGE_U32 * 4, m0, jb, c + 2, tid);

        const unsigned* cur = stage0 + (c % 3) * GRU_STAGE_U32;
        const unsigned* Ap = cur;
        const unsigned* Ah = cur + A_U32H;
        const unsigned* Bb = cur + GRU_BOFFH;
#pragma unroll
        for (int ks = 0; ks < 2; ks++) {
            int ko = ks * 8 + tig * 2;
            unsigned ap[2][4], ah[2][4];
#pragma unroll
            for (int mf = 0; mf < 2; mf++) {
                int r0 = wm + mf * 16 + gid;
                uint2 v0 = *(const uint2*)(Ap + r0 * RSTR + ko);
                uint2 v1 = *(const uint2*)(Ap + (r0 + 8) * RSTR + ko);
                ap[mf][0] = v0.x; ap[mf][1] = v1.x; ap[mf][2] = v0.y; ap[mf][3] = v1.y;
                uint2 w0 = *(const uint2*)(Ah + r0 * RSTR + ko);
                uint2 w1 = *(const uint2*)(Ah + (r0 + 8) * RSTR + ko);
                ah[mf][0] = w0.x; ah[mf][1] = w1.x; ah[mf][2] = w0.y; ah[mf][3] = w1.y;
            }
#pragma unroll
            for (int ni = 0; ni < 2; ni++) {
                int cb = (wn + ni * 8 + gid) * RSTR + ko;
                uint2 b;
                b = *(const uint2*)(Bb + 0 * B_U32H + cb);   /* Wir */
#pragma unroll
                for (int mf = 0; mf < 2; mf++) mma16(accR[mf][ni], ap[mf], b);
                b = *(const uint2*)(Bb + 1 * B_U32H + cb);   /* Whr */
#pragma unroll
                for (int mf = 0; mf < 2; mf++) mma16(accR[mf][ni], ah[mf], b);
                b = *(const uint2*)(Bb + 2 * B_U32H + cb);   /* Wiz */
#pragma unroll
                for (int mf = 0; mf < 2; mf++) mma16(accZ[mf][ni], ap[mf], b);
                b = *(const uint2*)(Bb + 3 * B_U32H + cb);   /* Whz */
#pragma unroll
                for (int mf = 0; mf < 2; mf++) mma16(accZ[mf][ni], ah[mf], b);
                b = *(const uint2*)(Bb + 4 * B_U32H + cb);   /* Win */
#pragma unroll
                for (int mf = 0; mf < 2; mf++) mma16(accN[mf][ni], ap[mf], b);
                b = *(const uint2*)(Bb + 5 * B_U32H + cb);   /* Whn */
#pragma unroll
                for (int mf = 0; mf < 2; mf++) mma16(accH[mf][ni], ah[mf], b);
            }
        }
    }

    /* epilogue: gates (h read in fp32) */
#pragma unroll
    for (int mf = 0; mf < 2; mf++) {
#pragma unroll
        for (int rp = 0; rp < 2; rp++) {
            int row = m0 + wm + mf * 16 + rp * 8 + gid;
            if (row >= NN) continue;
            const float* hrow = emb + (size_t)row * HH + jb * 64;
            float* orow = out + (size_t)row * HH + jb * 64;
#pragma unroll
            for (int ni = 0; ni < 2; ni++) {
                int c0 = wn + ni * 8 + tig * 2;
                float2 h2 = *(const float2*)(hrow + c0);
                float o[2];
#pragma unroll
                for (int e = 0; e < 2; e++) {
                    int q = rp * 2 + e;
                    int cl = c0 + e;
                    float r = sigmoidf_(accR[mf][ni][q] + bias_s[cl]);
                    float z = sigmoidf_(accZ[mf][ni][q] + bias_s[64 + cl]);
                    float n = tanhf(accN[mf][ni][q] + bias_s[128 + cl]
                                    + r * (accH[mf][ni][q] + bias_s[192 + cl]));
                    float h = e ? h2.y : h2.x;
                    o[e] = (1.f - z) * n + z * h;
                }
                *(float2*)(orow + c0) = make_float2(o[0], o[1]);
            }
        }
    }
}

/* ---------------- edge mma kernel ------------------------------------------
 * 256 threads, 8 warps, warp tile 32x32, CTA tile 128x64. 3-stage pipe.
 * 3 CTAs/SM so REDs overlap other CTAs' MMAs; v2 vectorized reductions.     */
__device__ __forceinline__ void edge_fill(uint32_t st, const int* __restrict__ ssrc,
                                          int jbg, int kc, int tid)
{
#pragma unroll
    for (int i = 0; i < 2; i++) {             /* A: 512 CPA16 */
        int idx = i * 256 + tid, r = idx >> 2, q = idx & 3;
        int nr = ssrc[r]; if (nr < 0) nr = 0;
        const unsigned* s = g_emb16 + (size_t)nr * 256 + kc * 16 + q * 4;
        CPA16(st + (r * RSTR + q * 4) * 4, (const void*)s);
    }
    {                                          /* B: 256 CPA16 */
        int row = tid >> 2, c = tid & 3;
        const char* src = (const char*)&g_wswe[(size_t)(jbg * 16 + kc) * B_GU32];
        CPA16(st + (A_U32H + row * RSTR + c * 4) * 4, src + tid * 16);
    }
    CPA_COMMIT();
}

__global__ __launch_bounds__(256, 3) void k_edge_mma(
    const int* __restrict__ src, const int* __restrict__ dst,
    const float* __restrict__ b_edge)
{
    int start = blockIdx.y * 128;
    if (start >= g_toff[TT]) return;
    int t = 0;
#pragma unroll
    for (int i = 1; i < TT; i++) if (start >= g_toff[i]) t = i;
    int jb8 = blockIdx.x;
    int jbg = t * 8 + jb8;

    extern __shared__ unsigned smu[];
    int* s_srow = (int*)smu;             /* 128 */
    int* s_dst  = (int*)smu + 128;       /* 128 */
    float* s_bias = (float*)smu + 256;   /* 64  */
    unsigned* stage0 = smu + 384;
    uint32_t st0 = smem_u32(stage0);

    int tid = threadIdx.x, lane = tid & 31, warp = tid >> 5;
    int gid = lane >> 2, tig = lane & 3;
    int wm = (warp >> 1) * 32, wn = (warp & 1) * 32;

    if (tid < 128) {
        int e = g_sorted[start + tid];
        s_srow[tid] = (e >= 0) ? src[e] : -1;
        s_dst[tid]  = (e >= 0) ? dst[e] : -1;
    }
    if (tid < 64) s_bias[tid] = b_edge[(size_t)t * HH + jb8 * 64 + tid];
    __syncthreads();

    float acc[2][4][4];
#pragma unroll
    for (int mf = 0; mf < 2; mf++)
#pragma unroll
        for (int ni = 0; ni < 4; ni++)
#pragma unroll
            for (int q = 0; q < 4; q++) acc[mf][ni][q] = 0.f;

    edge_fill(st0, s_srow, jbg, 0, tid);
    edge_fill(st0 + EDGE_STAGE_U32 * 4, s_srow, jbg, 1, tid);

    for (int c = 0; c < 16; c++) {
        if (c < 15) CPA_WAIT1(); else CPA_WAIT0();
        __syncthreads();
        if (c + 2 < 16)
            edge_fill(st0 + ((c + 2) % 3) * EDGE_STAGE_U32 * 4, s_srow, jbg, c + 2, tid);

        const unsigned* cur = stage0 + (c % 3) * EDGE_STAGE_U32;
        const unsigned* Ap = cur;
        const unsigned* Bb = cur + A_U32H;
#pragma unroll
        for (int ks = 0; ks < 2; ks++) {
            int ko = ks * 8 + tig * 2;
            unsigned ap[2][4];
#pragma unroll
            for (int mf = 0; mf < 2; mf++) {
                int r0 = wm + mf * 16 + gid;
                uint2 v0 = *(const uint2*)(Ap + r0 * RSTR + ko);
                uint2 v1 = *(const uint2*)(Ap + (r0 + 8) * RSTR + ko);
                ap[mf][0] = v0.x; ap[mf][1] = v1.x; ap[mf][2] = v0.y; ap[mf][3] = v1.y;
            }
#pragma unroll
            for (int ni = 0; ni < 4; ni++) {
                uint2 b = *(const uint2*)(Bb + (wn + ni * 8 + gid) * RSTR + ko);
#pragma unroll
                for (int mf = 0; mf < 2; mf++) mma16(acc[mf][ni], ap[mf], b);
            }
        }
    }

    /* epilogue: bias + vectorized scatter reduction */
#pragma unroll
    for (int mf = 0; mf < 2; mf++) {
#pragma unroll
        for (int rp = 0; rp < 2; rp++) {
            int arow = wm + mf * 16 + rp * 8 + gid;
            int d = s_dst[arow];
            if (d < 0) continue;
            float* prow = g_proposed + (size_t)d * HH + jb8 * 64;
#pragma unroll
            for (int ni = 0; ni < 4; ni++) {
                int c0 = wn + ni * 8 + tig * 2;
                red2(prow + c0,
                     acc[mf][ni][rp * 2]     + s_bias[c0],
                     acc[mf][ni][rp * 2 + 1] + s_bias[c0 + 1]);
            }
        }
    }
}

/* ---------------- launch --------------------------------------------------- */
extern "C" void kernel_launch(void* const* d_in, const int* in_sizes, int n_in,
                              void* d_out, int out_size)
{
    int s = (n_in >= 18) ? 2 : 0;

    const float* emb    = (const float*)d_in[0];
    const int*   src    = (const int*)d_in[1];
    const int*   dst    = (const int*)d_in[2];
    const int*   et     = (const int*)d_in[3];
    const float* W_edge = (const float*)d_in[4 + s];
    const float* b_edge = (const float*)d_in[5 + s];
    const float* Wir    = (const float*)d_in[6 + s];
    const float* Wiz    = (const float*)d_in[7 + s];
    const float* Win    = (const float*)d_in[8 + s];
    const float* bir    = (const float*)d_in[9 + s];
    const float* biz    = (const float*)d_in[10 + s];
    const float* bin    = (const float*)d_in[11 + s];
    const float* Whr    = (const float*)d_in[12 + s];
    const float* Whz    = (const float*)d_in[13 + s];
    const float* Whn    = (const float*)d_in[14 + s];
    const float* bhn    = (const float*)d_in[15 + s];
    float* out = (float*)d_out;

    float* d_prop;    cudaGetSymbolAddress((void**)&d_prop, g_proposed);
    unsigned* d_e16;  cudaGetSymbolAddress((void**)&d_e16, g_emb16);
    unsigned* d_p16;  cudaGetSymbolAddress((void**)&d_p16, g_prop16);

    static int attr_done = 0;
    if (!attr_done) {
        cudaFuncSetAttribute(k_gru_mma,  cudaFuncAttributeMaxDynamicSharedMemorySize, GRU_SMEMH);
        cudaFuncSetAttribute(k_edge_mma, cudaFuncAttributeMaxDynamicSharedMemorySize, EDGE_SMEMH);
        attr_done = 1;
    }

    k_init_proposed<<<(NN * HH / 4 + 255) / 256, 256>>>();
    k_init_meta<<<(SORT_CAP + 255) / 256, 256>>>();
    k_hist<<<(EE + 255) / 256, 256>>>(et);
    k_offsets<<<1, 32>>>();
    k_scatter<<<(EE + 255) / 256, 256>>>(et);

    k_prep_gru<<<dim3(16, 8, 6), 256>>>(Wir, Whr, Wiz, Whz, Win, Whn);
    k_prep_edge<<<dim3(16, 48), 256>>>(W_edge);
    k_cvt16<<<(NN * 32 + 255) / 256, 256>>>(emb, d_e16);

    k_edge_mma<<<dim3(8, EGRP), 256, EDGE_SMEMH>>>(src, dst, b_edge);

    k_cvt16<<<(NN * 32 + 255) / 256, 256>>>(d_prop, d_p16);
    k_gru_mma<<<dim3(8, MBLK), 512, GRU_SMEMH>>>(emb, bir, biz, bin, bhn, out);
}

// round 10
// speedup vs baseline: 4.3599x; 1.0018x over previous
#include <cuda_runtime.h>
#include <cuda_fp16.h>
#include <cstdint>
#include <math.h>

#define NN 50000
#define EE 100000
#define HH 512
#define TT 6
#define NTILE 3128                     /* 391 m-blocks x 8 jb */
#define EGRP 397                       /* ceil((EE + TT*256)/256) */
#define SORT_CAP (EE + TT * 256)

#define RSTR 24                        /* u32 stride per 32-k fp16 row in smem */
#define B_GU32 (64 * 16)               /* global B blob chunk: 64 rows x 16 u32 */

#define A_U32H   (128 * RSTR)                           /* 3072 */
#define B_U32H   (64 * RSTR)                            /* 1536 */
#define GRU_BOFFH (2 * A_U32H)                          /* 6144 */
#define GRU_STAGE_U32 (GRU_BOFFH + 6 * B_U32H)          /* 15360 */
#define GRU_HDR_U32  320
#define GRU_SMEMH ((GRU_HDR_U32 + 3 * GRU_STAGE_U32) * 4)   /* 185600 B */

#define EDGE_A_U32 (256 * RSTR)                         /* 6144 */
#define EDGE_STAGE_U32 (EDGE_A_U32 + B_U32H)            /* 7680 */
#define EDGE_HDR_U32 640
#define EDGE_SMEMH ((EDGE_HDR_U32 + 3 * EDGE_STAGE_U32) * 4) /* 94720 B */

/* ---------------- static device scratch ----------------------------------- */
__device__ float    g_proposed[(size_t)NN * HH];
__device__ unsigned g_emb16[(size_t)NN * 256];    /* fp16 interleaved, 256 u32/row */
__device__ unsigned g_prop16[(size_t)NN * 256];   /* fp16 interleaved, 256 u32/row */
__device__ unsigned g_wswg[(size_t)6 * 8 * 16 * B_GU32];
__device__ unsigned g_wswe[(size_t)48 * 16 * B_GU32];
__device__ int g_sorted[SORT_CAP];
__device__ int g_tcount[TT];
__device__ int g_tcur[TT];
__device__ int g_toff[TT + 1];
__device__ int g_hdone;
__device__ int g_gtick;

/* ---------------- helpers -------------------------------------------------- */
__device__ __forceinline__ unsigned pk2h(float lo, float hi) {
    unsigned u;
    asm("cvt.rn.f16x2.f32 %0, %1, %2;" : "=r"(u) : "f"(hi), "f"(lo));
    return u;
}
__device__ __forceinline__ float sigmoidf_(float x) { return 1.0f / (1.0f + expf(-x)); }

__device__ __forceinline__ void mma16(float c[4], const unsigned a[4], uint2 b) {
    asm volatile(
        "mma.sync.aligned.m16n8k16.row.col.f32.f16.f16.f32 "
        "{%0,%1,%2,%3},{%4,%5,%6,%7},{%8,%9},{%0,%1,%2,%3};"
        : "+f"(c[0]), "+f"(c[1]), "+f"(c[2]), "+f"(c[3])
        : "r"(a[0]), "r"(a[1]), "r"(a[2]), "r"(a[3]), "r"(b.x), "r"(b.y));
}

__device__ __forceinline__ void red2(float* p, float v0, float v1) {
    asm volatile("red.global.add.v2.f32 [%0], {%1, %2};"
                 :: "l"(p), "f"(v0), "f"(v1) : "memory");
}

#define CPA16(d, s) asm volatile("cp.async.ca.shared.global [%0], [%1], 16;" :: "r"(d), "l"(s))
#define CPA_COMMIT() asm volatile("cp.async.commit_group;" ::: "memory")
#define CPA_WAIT0()  asm volatile("cp.async.wait_group 0;" ::: "memory")
#define CPA_WAIT1()  asm volatile("cp.async.wait_group 1;" ::: "memory")

__device__ __forceinline__ uint32_t smem_u32(const void* p) {
    uint32_t a;
    asm("{ .reg .u64 t; cvta.to.shared.u64 t, %1; cvt.u32.u64 %0, t; }" : "=r"(a) : "l"(p));
    return a;
}

/* ---------------- init + meta (merged) ------------------------------------- */
__global__ void k_init(void) {
    size_t i = (size_t)blockIdx.x * blockDim.x + threadIdx.x;
    size_t n4 = (size_t)NN * HH / 4;
    if (i < n4) ((float4*)g_proposed)[i] = make_float4(0.f, 0.f, 0.f, 0.f);
    if (i < SORT_CAP) g_sorted[i] = -1;
    if (i < TT) { g_tcount[i] = 0; g_tcur[i] = 0; }
    if (i == 0) { g_hdone = 0; g_gtick = 0; }
}

/* hist with folded offsets (last block computes prefix) */
__global__ void k_hist(const int* __restrict__ et) {
    int e = blockIdx.x * blockDim.x + threadIdx.x;
    if (e < EE) atomicAdd(&g_tcount[et[e]], 1);
    __syncthreads();
    if (threadIdx.x == 0) {
        __threadfence();
        int old = atomicAdd(&g_hdone, 1);
        if (old == gridDim.x - 1) {
            int off = 0;
            for (int t = 0; t < TT; t++) {
                g_toff[t] = off;
                off += ((g_tcount[t] + 255) >> 8) << 8;   /* pad to 256 */
            }
            g_toff[TT] = off;
            __threadfence();
        }
    }
}

__global__ void k_scatter(const int* __restrict__ et) {
    int e = blockIdx.x * blockDim.x + threadIdx.x;
    if (e < EE) {
        int t = et[e];
        int pos = g_toff[t] + atomicAdd(&g_tcur[t], 1);
        g_sorted[pos] = e;
    }
}

/* ---------------- fp32 -> interleaved fp16 conversion ----------------------- */
__global__ void k_cvt16(const float* __restrict__ src, unsigned* __restrict__ dst) {
    size_t i = (size_t)blockIdx.x * blockDim.x + threadIdx.x;
    if (i >= (size_t)NN * 32) return;
    const float4* s4 = (const float4*)(src + i * 16);
    float4 f0 = s4[0], f1 = s4[1], f2 = s4[2], f3 = s4[3];
    unsigned o[8];
    o[0] = pk2h(f0.x, f0.y); o[2] = pk2h(f0.z, f0.w);
    o[4] = pk2h(f1.x, f1.y); o[6] = pk2h(f1.z, f1.w);
    o[1] = pk2h(f2.x, f2.y); o[3] = pk2h(f2.z, f2.w);
    o[5] = pk2h(f3.x, f3.y); o[7] = pk2h(f3.z, f3.w);
    uint4* d4 = (uint4*)(dst + i * 8);
    d4[0] = make_uint4(o[0], o[1], o[2], o[3]);
    d4[1] = make_uint4(o[4], o[5], o[6], o[7]);
}

/* ---------------- weight prep: fp16 interleaved blobs ---------------------- */
__global__ void k_prep_gru(const float* __restrict__ W0, const float* __restrict__ W1,
                           const float* __restrict__ W2, const float* __restrict__ W3,
                           const float* __restrict__ W4, const float* __restrict__ W5) {
    int kc = blockIdx.x, jb = blockIdx.y, mat = blockIdx.z;
    const float* Ws[6] = {W0, W1, W2, W3, W4, W5};
    const float* W = Ws[mat];
    int tid = threadIdx.x, n = tid & 63, kg = tid >> 6;
    unsigned* dst = &g_wswg[(size_t)((mat * 8 + jb) * 16 + kc) * B_GU32];
#pragma unroll
    for (int p = 0; p < 4; p++) {
        int jp = kg * 4 + p;
        int kk = kc * 32 + jp * 2;
        float v0 = W[(size_t)kk * HH + jb * 64 + n];
        float v1 = W[(size_t)(kk + 1) * HH + jb * 64 + n];
        int g = jp >> 3, jj = jp & 7;
        dst[n * 16 + g * 8 + 2 * (jj & 3) + (jj >> 2)] = pk2h(v0, v1);
    }
}
__global__ void k_prep_edge(const float* __restrict__ W) {
    int kc = blockIdx.x, jb = blockIdx.y;
    int tid = threadIdx.x, n = tid & 63, kg = tid >> 6;
    unsigned* dst = &g_wswe[(size_t)(jb * 16 + kc) * B_GU32];
#pragma unroll
    for (int p = 0; p < 4; p++) {
        int jp = kg * 4 + p;
        int kk = kc * 32 + jp * 2;
        float v0 = W[(size_t)kk * (TT * HH) + jb * 64 + n];
        float v1 = W[(size_t)(kk + 1) * (TT * HH) + jb * 64 + n];
        int g = jp >> 3, jj = jp & 7;
        dst[n * 16 + g * 8 + 2 * (jj & 3) + (jj >> 2)] = pk2h(v0, v1);
    }
}

/* ---------------- fused GRU mma kernel (persistent) -------------------------
 * 512 threads, 16 warps, warp tile 32x16, tile 128x64, 3-stage pipe.
 * 160 resident CTAs pull tile tickets (jb fastest) from g_gtick.            */
__device__ __forceinline__ void gru_fill(uint32_t st, int m0, int jb, int kc, int tid)
{
#pragma unroll
    for (int i = 0; i < 2; i++) {             /* A: 1024 CPA16 */
        int idx = i * 512 + tid;
        int mat = idx >> 9, rq = idx & 511, r = rq >> 2, q = rq & 3;
        int rg = m0 + r; if (rg > NN - 1) rg = NN - 1;
        const unsigned* s = (mat ? g_emb16 : g_prop16) + (size_t)rg * 256 + kc * 16 + q * 4;
        CPA16(st + (mat * A_U32H + r * RSTR + q * 4) * 4, (const void*)s);
    }
#pragma unroll
    for (int i = 0; i < 3; i++) {             /* B: 1536 CPA16 */
        int gidx = i * 512 + tid;
        int m_ = gidx >> 8, idx = gidx & 255, row = idx >> 2, c = idx & 3;
        const char* src = (const char*)&g_wswg[(size_t)((m_ * 8 + jb) * 16 + kc) * B_GU32];
        CPA16(st + (GRU_BOFFH + m_ * B_U32H + row * RSTR + c * 4) * 4, src + idx * 16);
    }
    CPA_COMMIT();
}

__global__ __launch_bounds__(512, 1) void k_gru_mma(
    const float* __restrict__ emb,
    const float* __restrict__ bir, const float* __restrict__ biz,
    const float* __restrict__ bin, const float* __restrict__ bhn,
    float* __restrict__ out)
{
    extern __shared__ unsigned smu[];
    float* bias_s = (float*)smu;                 /* 256 floats */
    int*   s_tick = (int*)(smu + 256);
    unsigned* stage0 = smu + GRU_HDR_U32;
    uint32_t st0 = smem_u32(stage0);

    int tid = threadIdx.x, lane = tid & 31, warp = tid >> 5;
    int gid = lane >> 2, tig = lane & 3;
    int wm = (warp >> 2) * 32, wn = (warp & 3) * 16;

    for (;;) {
        if (tid == 0) *s_tick = atomicAdd(&g_gtick, 1);
        __syncthreads();
        int t = *s_tick;
        if (t >= NTILE) return;
        int jb = t & 7, m0 = (t >> 3) * 128;

        if (tid < 256) {
            const float* ba[4] = {bir, biz, bin, bhn};
            bias_s[tid] = ba[tid >> 6][jb * 64 + (tid & 63)];
        }

        float accR[2][2][4], accZ[2][2][4], accN[2][2][4], accH[2][2][4];
#pragma unroll
        for (int mf = 0; mf < 2; mf++)
#pragma unroll
            for (int ni = 0; ni < 2; ni++)
#pragma unroll
                for (int q = 0; q < 4; q++) {
                    accR[mf][ni][q] = 0.f; accZ[mf][ni][q] = 0.f;
                    accN[mf][ni][q] = 0.f; accH[mf][ni][q] = 0.f;
                }

        gru_fill(st0, m0, jb, 0, tid);
        gru_fill(st0 + GRU_STAGE_U32 * 4, m0, jb, 1, tid);

        for (int c = 0; c < 16; c++) {
            if (c < 15) CPA_WAIT1(); else CPA_WAIT0();
            __syncthreads();
            if (c + 2 < 16)
                gru_fill(st0 + ((c + 2) % 3) * GRU_STAGE_U32 * 4, m0, jb, c + 2, tid);

            const unsigned* cur = stage0 + (c % 3) * GRU_STAGE_U32;
            const unsigned* Ap = cur;
            const unsigned* Ah = cur + A_U32H;
            const unsigned* Bb = cur + GRU_BOFFH;
#pragma unroll
            for (int ks = 0; ks < 2; ks++) {
                int ko = ks * 8 + tig * 2;
                unsigned ap[2][4], ah[2][4];
#pragma unroll
                for (int mf = 0; mf < 2; mf++) {
                    int r0 = wm + mf * 16 + gid;
                    uint2 v0 = *(const uint2*)(Ap + r0 * RSTR + ko);
                    uint2 v1 = *(const uint2*)(Ap + (r0 + 8) * RSTR + ko);
                    ap[mf][0] = v0.x; ap[mf][1] = v1.x; ap[mf][2] = v0.y; ap[mf][3] = v1.y;
                    uint2 w0 = *(const uint2*)(Ah + r0 * RSTR + ko);
                    uint2 w1 = *(const uint2*)(Ah + (r0 + 8) * RSTR + ko);
                    ah[mf][0] = w0.x; ah[mf][1] = w1.x; ah[mf][2] = w0.y; ah[mf][3] = w1.y;
                }
#pragma unroll
                for (int ni = 0; ni < 2; ni++) {
                    int cb = (wn + ni * 8 + gid) * RSTR + ko;
                    uint2 b;
                    b = *(const uint2*)(Bb + 0 * B_U32H + cb);   /* Wir */
#pragma unroll
                    for (int mf = 0; mf < 2; mf++) mma16(accR[mf][ni], ap[mf], b);
                    b = *(const uint2*)(Bb + 1 * B_U32H + cb);   /* Whr */
#pragma unroll
                    for (int mf = 0; mf < 2; mf++) mma16(accR[mf][ni], ah[mf], b);
                    b = *(const uint2*)(Bb + 2 * B_U32H + cb);   /* Wiz */
#pragma unroll
                    for (int mf = 0; mf < 2; mf++) mma16(accZ[mf][ni], ap[mf], b);
                    b = *(const uint2*)(Bb + 3 * B_U32H + cb);   /* Whz */
#pragma unroll
                    for (int mf = 0; mf < 2; mf++) mma16(accZ[mf][ni], ah[mf], b);
                    b = *(const uint2*)(Bb + 4 * B_U32H + cb);   /* Win */
#pragma unroll
                    for (int mf = 0; mf < 2; mf++) mma16(accN[mf][ni], ap[mf], b);
                    b = *(const uint2*)(Bb + 5 * B_U32H + cb);   /* Whn */
#pragma unroll
                    for (int mf = 0; mf < 2; mf++) mma16(accH[mf][ni], ah[mf], b);
                }
            }
        }

        /* epilogue: gates (h read in fp32) */
#pragma unroll
        for (int mf = 0; mf < 2; mf++) {
#pragma unroll
            for (int rp = 0; rp < 2; rp++) {
                int row = m0 + wm + mf * 16 + rp * 8 + gid;
                if (row >= NN) continue;
                const float* hrow = emb + (size_t)row * HH + jb * 64;
                float* orow = out + (size_t)row * HH + jb * 64;
#pragma unroll
                for (int ni = 0; ni < 2; ni++) {
                    int c0 = wn + ni * 8 + tig * 2;
                    float2 h2 = *(const float2*)(hrow + c0);
                    float o[2];
#pragma unroll
                    for (int e = 0; e < 2; e++) {
                        int q = rp * 2 + e;
                        int cl = c0 + e;
                        float r = sigmoidf_(accR[mf][ni][q] + bias_s[cl]);
                        float z = sigmoidf_(accZ[mf][ni][q] + bias_s[64 + cl]);
                        float n = tanhf(accN[mf][ni][q] + bias_s[128 + cl]
                                        + r * (accH[mf][ni][q] + bias_s[192 + cl]));
                        float h = e ? h2.y : h2.x;
                        o[e] = (1.f - z) * n + z * h;
                    }
                    *(float2*)(orow + c0) = make_float2(o[0], o[1]);
                }
            }
        }
        __syncthreads();     /* protect bias_s / stages before next tile */
    }
}

/* ---------------- edge mma kernel ------------------------------------------
 * 256 threads, 8 warps, warp tile 64x32, CTA tile 256x64. 3-stage pipe,
 * 2 CTAs/SM. Type groups padded to 256.                                     */
__device__ __forceinline__ void edge_fill(uint32_t st, const int* __restrict__ ssrc,
                                          int jbg, int kc, int tid)
{
#pragma unroll
    for (int i = 0; i < 4; i++) {             /* A: 1024 CPA16 */
        int idx = i * 256 + tid, r = idx >> 2, q = idx & 3;
        int nr = ssrc[r]; if (nr < 0) nr = 0;
        const unsigned* s = g_emb16 + (size_t)nr * 256 + kc * 16 + q * 4;
        CPA16(st + (r * RSTR + q * 4) * 4, (const void*)s);
    }
    {                                          /* B: 256 CPA16 */
        int row = tid >> 2, c = tid & 3;
        const char* src = (const char*)&g_wswe[(size_t)(jbg * 16 + kc) * B_GU32];
        CPA16(st + (EDGE_A_U32 + row * RSTR + c * 4) * 4, src + tid * 16);
    }
    CPA_COMMIT();
}

__global__ __launch_bounds__(256, 2) void k_edge_mma(
    const int* __restrict__ src, const int* __restrict__ dst,
    const float* __restrict__ b_edge)
{
    int start = blockIdx.y * 256;
    if (start >= g_toff[TT]) return;
    int t = 0;
#pragma unroll
    for (int i = 1; i < TT; i++) if (start >= g_toff[i]) t = i;
    int jb8 = blockIdx.x;
    int jbg = t * 8 + jb8;

    extern __shared__ unsigned smu[];
    int* s_srow = (int*)smu;             /* 256 */
    int* s_dst  = (int*)smu + 256;       /* 256 */
    float* s_bias = (float*)smu + 512;   /* 64  */
    unsigned* stage0 = smu + EDGE_HDR_U32;
    uint32_t st0 = smem_u32(stage0);

    int tid = threadIdx.x, lane = tid & 31, warp = tid >> 5;
    int gid = lane >> 2, tig = lane & 3;
    int wm = (warp >> 1) * 64, wn = (warp & 1) * 32;

    {
        int e = g_sorted[start + tid];
        s_srow[tid] = (e >= 0) ? src[e] : -1;
        s_dst[tid]  = (e >= 0) ? dst[e] : -1;
        int e2 = g_sorted[start + 128 + tid];
        /* handled below for tid<128 only pattern; do full 256 rows: */
    }
    /* load both halves explicitly */
    {
        int e = g_sorted[start + tid];
        s_srow[tid] = (e >= 0) ? src[e] : -1;
        s_dst[tid]  = (e >= 0) ? dst[e] : -1;
    }
    if (tid < 64) s_bias[tid] = b_edge[(size_t)t * HH + jb8 * 64 + tid];
    __syncthreads();

    float acc[4][4][4];
#pragma unroll
    for (int mf = 0; mf < 4; mf++)
#pragma unroll
        for (int ni = 0; ni < 4; ni++)
#pragma unroll
            for (int q = 0; q < 4; q++) acc[mf][ni][q] = 0.f;

    edge_fill(st0, s_srow, jbg, 0, tid);
    edge_fill(st0 + EDGE_STAGE_U32 * 4, s_srow, jbg, 1, tid);

    for (int c = 0; c < 16; c++) {
        if (c < 15) CPA_WAIT1(); else CPA_WAIT0();
        __syncthreads();
        if (c + 2 < 16)
            edge_fill(st0 + ((c + 2) % 3) * EDGE_STAGE_U32 * 4, s_srow, jbg, c + 2, tid);

        const unsigned* cur = stage0 + (c % 3) * EDGE_STAGE_U32;
        const unsigned* Ap = cur;
        const unsigned* Bb = cur + EDGE_A_U32;
#pragma unroll
        for (int ks = 0; ks < 2; ks++) {
            int ko = ks * 8 + tig * 2;
            unsigned ap[4][4];
#pragma unroll
            for (int mf = 0; mf < 4; mf++) {
                int r0 = wm + mf * 16 + gid;
                uint2 v0 = *(const uint2*)(Ap + r0 * RSTR + ko);
                uint2 v1 = *(const uint2*)(Ap + (r0 + 8) * RSTR + ko);
                ap[mf][0] = v0.x; ap[mf][1] = v1.x; ap[mf][2] = v0.y; ap[mf][3] = v1.y;
            }
#pragma unroll
            for (int ni = 0; ni < 4; ni++) {
                uint2 b = *(const uint2*)(Bb + (wn + ni * 8 + gid) * RSTR + ko);
#pragma unroll
                for (int mf = 0; mf < 4; mf++) mma16(acc[mf][ni], ap[mf], b);
            }
        }
    }

    /* wait: s_srow still read by fills of earlier stages — done. epilogue: */
#pragma unroll
    for (int mf = 0; mf < 4; mf++) {
#pragma unroll
        for (int rp = 0; rp < 2; rp++) {
            int arow = wm + mf * 16 + rp * 8 + gid;
            int d = s_dst[arow];
            if (d < 0) continue;
            float* prow = g_proposed + (size_t)d * HH + jb8 * 64;
#pragma unroll
            for (int ni = 0; ni < 4; ni++) {
                int c0 = wn + ni * 8 + tig * 2;
                red2(prow + c0,
                     acc[mf][ni][rp * 2]     + s_bias[c0],
                     acc[mf][ni][rp * 2 + 1] + s_bias[c0 + 1]);
            }
        }
    }
}

/* ---------------- launch --------------------------------------------------- */
extern "C" void kernel_launch(void* const* d_in, const int* in_sizes, int n_in,
                              void* d_out, int out_size)
{
    int s = (n_in >= 18) ? 2 : 0;

    const float* emb    = (const float*)d_in[0];
    const int*   src    = (const int*)d_in[1];
    const int*   dst    = (const int*)d_in[2];
    const int*   et     = (const int*)d_in[3];
    const float* W_edge = (const float*)d_in[4 + s];
    const float* b_edge = (const float*)d_in[5 + s];
    const float* Wir    = (const float*)d_in[6 + s];
    const float* Wiz    = (const float*)d_in[7 + s];
    const float* Win    = (const float*)d_in[8 + s];
    const float* bir    = (const float*)d_in[9 + s];
    const float* biz    = (const float*)d_in[10 + s];
    const float* bin    = (const float*)d_in[11 + s];
    const float* Whr    = (const float*)d_in[12 + s];
    const float* Whz    = (const float*)d_in[13 + s];
    const float* Whn    = (const float*)d_in[14 + s];
    const float* bhn    = (const float*)d_in[15 + s];
    float* out = (float*)d_out;

    float* d_prop;    cudaGetSymbolAddress((void**)&d_prop, g_proposed);
    unsigned* d_e16;  cudaGetSymbolAddress((void**)&d_e16, g_emb16);
    unsigned* d_p16;  cudaGetSymbolAddress((void**)&d_p16, g_prop16);

    static int attr_done = 0;
    if (!attr_done) {
        cudaFuncSetAttribute(k_gru_mma,  cudaFuncAttributeMaxDynamicSharedMemorySize, GRU_SMEMH);
        cudaFuncSetAttribute(k_edge_mma, cudaFuncAttributeMaxDynamicSharedMemorySize, EDGE_SMEMH);
        attr_done = 1;
    }

    k_init<<<(NN * HH / 4 + 255) / 256, 256>>>();
    k_hist<<<(EE + 255) / 256, 256>>>(et);
    k_scatter<<<(EE + 255) / 256, 256>>>(et);

    k_prep_gru<<<dim3(16, 8, 6), 256>>>(Wir, Whr, Wiz, Whz, Win, Whn);
    k_prep_edge<<<dim3(16, 48), 256>>>(W_edge);
    k_cvt16<<<(NN * 32 + 255) / 256, 256>>>(emb, d_e16);

    k_edge_mma<<<dim3(8, EGRP), 256, EDGE_SMEMH>>>(src, dst, b_edge);

    k_cvt16<<<(NN * 32 + 255) / 256, 256>>>(d_prop, d_p16);
    k_gru_mma<<<160, 512, GRU_SMEMH>>>(emb, bir, biz, bin, bhn, out);
}

// round 11
// speedup vs baseline: 4.4868x; 1.0291x over previous
#include <cuda_runtime.h>
#include <cuda_fp16.h>
#include <cstdint>
#include <math.h>

#define NN 50000
#define EE 100000
#define HH 512
#define TT 6
#define NTILE 3128                     /* 391 m-blocks x 8 jb */
#define EGRP 397                       /* ceil((EE + TT*256)/256) */
#define SORT_CAP (EE + TT * 256)

#define RSTR 24                        /* u32 stride per 32-k fp16 row in smem */
#define B_GU32 (64 * 16)               /* global B blob chunk: 64 rows x 16 u32 */

#define A_U32H   (128 * RSTR)                           /* 3072 */
#define B_U32H   (64 * RSTR)                            /* 1536 */
#define GRU_BOFFH (2 * A_U32H)                          /* 6144 */
#define GRU_STAGE_U32 (GRU_BOFFH + 6 * B_U32H)          /* 15360 */
#define GRU_HDR_U32  320
#define GRU_SMEMH ((GRU_HDR_U32 + 3 * GRU_STAGE_U32) * 4)   /* 185600 B */

#define EDGE_A_U32 (256 * RSTR)                         /* 6144 */
#define EDGE_STAGE_U32 (EDGE_A_U32 + B_U32H)            /* 7680 */
#define EDGE_HDR_U32 640
#define EDGE_SMEMH ((EDGE_HDR_U32 + 3 * EDGE_STAGE_U32) * 4) /* 94720 B */

/* ---------------- static device scratch ----------------------------------- */
__device__ unsigned g_emb16[(size_t)NN * 256];    /* fp16 interleaved, 256 u32/row */
__device__ unsigned g_prop16[(size_t)NN * 256];   /* fp16 interleaved accumulator  */
__device__ unsigned g_wswg[(size_t)6 * 8 * 16 * B_GU32];
__device__ unsigned g_wswe[(size_t)48 * 16 * B_GU32];
__device__ int g_sorted[SORT_CAP];
__device__ int g_tcount[TT];
__device__ int g_tcur[TT];
__device__ int g_toff[TT + 1];
__device__ int g_hdone;
__device__ int g_gtick;

/* ---------------- helpers -------------------------------------------------- */
__device__ __forceinline__ unsigned pk2h(float lo, float hi) {
    unsigned u;
    asm("cvt.rn.f16x2.f32 %0, %1, %2;" : "=r"(u) : "f"(hi), "f"(lo));
    return u;
}
__device__ __forceinline__ float sigmoidf_(float x) { return 1.0f / (1.0f + expf(-x)); }

__device__ __forceinline__ void mma16(float c[4], const unsigned a[4], uint2 b) {
    asm volatile(
        "mma.sync.aligned.m16n8k16.row.col.f32.f16.f16.f32 "
        "{%0,%1,%2,%3},{%4,%5,%6,%7},{%8,%9},{%0,%1,%2,%3};"
        : "+f"(c[0]), "+f"(c[1]), "+f"(c[2]), "+f"(c[3])
        : "r"(a[0]), "r"(a[1]), "r"(a[2]), "r"(a[3]), "r"(b.x), "r"(b.y));
}

__device__ __forceinline__ void redh2(unsigned* p, unsigned v) {
    asm volatile("red.global.add.noftz.f16x2 [%0], %1;"
                 :: "l"(p), "r"(v) : "memory");
}

#define CPA16(d, s) asm volatile("cp.async.ca.shared.global [%0], [%1], 16;" :: "r"(d), "l"(s))
#define CPA_COMMIT() asm volatile("cp.async.commit_group;" ::: "memory")
#define CPA_WAIT0()  asm volatile("cp.async.wait_group 0;" ::: "memory")
#define CPA_WAIT1()  asm volatile("cp.async.wait_group 1;" ::: "memory")

__device__ __forceinline__ uint32_t smem_u32(const void* p) {
    uint32_t a;
    asm("{ .reg .u64 t; cvta.to.shared.u64 t, %1; cvt.u32.u64 %0, t; }" : "=r"(a) : "l"(p));
    return a;
}

/* ---------------- init + meta (merged) ------------------------------------- */
__global__ void k_init(void) {
    size_t i = (size_t)blockIdx.x * blockDim.x + threadIdx.x;
    size_t n4 = (size_t)NN * 64;                   /* uint4 count of g_prop16 */
    if (i < n4) ((uint4*)g_prop16)[i] = make_uint4(0u, 0u, 0u, 0u);
    if (i < SORT_CAP) g_sorted[i] = -1;
    if (i < TT) { g_tcount[i] = 0; g_tcur[i] = 0; }
    if (i == 0) { g_hdone = 0; g_gtick = 0; }
}

/* hist with folded offsets (last block computes prefix) */
__global__ void k_hist(const int* __restrict__ et) {
    int e = blockIdx.x * blockDim.x + threadIdx.x;
    if (e < EE) atomicAdd(&g_tcount[et[e]], 1);
    __syncthreads();
    if (threadIdx.x == 0) {
        __threadfence();
        int old = atomicAdd(&g_hdone, 1);
        if (old == gridDim.x - 1) {
            int off = 0;
            for (int t = 0; t < TT; t++) {
                g_toff[t] = off;
                off += ((g_tcount[t] + 255) >> 8) << 8;   /* pad to 256 */
            }
            g_toff[TT] = off;
            __threadfence();
        }
    }
}

__global__ void k_scatter(const int* __restrict__ et) {
    int e = blockIdx.x * blockDim.x + threadIdx.x;
    if (e < EE) {
        int t = et[e];
        int pos = g_toff[t] + atomicAdd(&g_tcur[t], 1);
        g_sorted[pos] = e;
    }
}

/* ---------------- fp32 -> interleaved fp16 conversion ----------------------- */
__global__ void k_cvt16(const float* __restrict__ src, unsigned* __restrict__ dst) {
    size_t i = (size_t)blockIdx.x * blockDim.x + threadIdx.x;
    if (i >= (size_t)NN * 32) return;
    const float4* s4 = (const float4*)(src + i * 16);
    float4 f0 = s4[0], f1 = s4[1], f2 = s4[2], f3 = s4[3];
    unsigned o[8];
    o[0] = pk2h(f0.x, f0.y); o[2] = pk2h(f0.z, f0.w);
    o[4] = pk2h(f1.x, f1.y); o[6] = pk2h(f1.z, f1.w);
    o[1] = pk2h(f2.x, f2.y); o[3] = pk2h(f2.z, f2.w);
    o[5] = pk2h(f3.x, f3.y); o[7] = pk2h(f3.z, f3.w);
    uint4* d4 = (uint4*)(dst + i * 8);
    d4[0] = make_uint4(o[0], o[1], o[2], o[3]);
    d4[1] = make_uint4(o[4], o[5], o[6], o[7]);
}

/* ---------------- weight prep: fp16 interleaved blobs ---------------------- */
__global__ void k_prep_gru(const float* __restrict__ W0, const float* __restrict__ W1,
                           const float* __restrict__ W2, const float* __restrict__ W3,
                           const float* __restrict__ W4, const float* __restrict__ W5) {
    int kc = blockIdx.x, jb = blockIdx.y, mat = blockIdx.z;
    const float* Ws[6] = {W0, W1, W2, W3, W4, W5};
    const float* W = Ws[mat];
    int tid = threadIdx.x, n = tid & 63, kg = tid >> 6;
    unsigned* dst = &g_wswg[(size_t)((mat * 8 + jb) * 16 + kc) * B_GU32];
#pragma unroll
    for (int p = 0; p < 4; p++) {
        int jp = kg * 4 + p;
        int kk = kc * 32 + jp * 2;
        float v0 = W[(size_t)kk * HH + jb * 64 + n];
        float v1 = W[(size_t)(kk + 1) * HH + jb * 64 + n];
        int g = jp >> 3, jj = jp & 7;
        dst[n * 16 + g * 8 + 2 * (jj & 3) + (jj >> 2)] = pk2h(v0, v1);
    }
}
__global__ void k_prep_edge(const float* __restrict__ W) {
    int kc = blockIdx.x, jb = blockIdx.y;
    int tid = threadIdx.x, n = tid & 63, kg = tid >> 6;
    unsigned* dst = &g_wswe[(size_t)(jb * 16 + kc) * B_GU32];
#pragma unroll
    for (int p = 0; p < 4; p++) {
        int jp = kg * 4 + p;
        int kk = kc * 32 + jp * 2;
        float v0 = W[(size_t)kk * (TT * HH) + jb * 64 + n];
        float v1 = W[(size_t)(kk + 1) * (TT * HH) + jb * 64 + n];
        int g = jp >> 3, jj = jp & 7;
        dst[n * 16 + g * 8 + 2 * (jj & 3) + (jj >> 2)] = pk2h(v0, v1);
    }
}

/* ---------------- fused GRU mma kernel (persistent) -------------------------
 * 512 threads, 16 warps, warp tile 32x16, tile 128x64, 3-stage pipe.
 * 160 resident CTAs pull tile tickets (jb fastest) from g_gtick.            */
__device__ __forceinline__ void gru_fill(uint32_t st, int m0, int jb, int kc, int tid)
{
#pragma unroll
    for (int i = 0; i < 2; i++) {             /* A: 1024 CPA16 */
        int idx = i * 512 + tid;
        int mat = idx >> 9, rq = idx & 511, r = rq >> 2, q = rq & 3;
        int rg = m0 + r; if (rg > NN - 1) rg = NN - 1;
        const unsigned* s = (mat ? g_emb16 : g_prop16) + (size_t)rg * 256 + kc * 16 + q * 4;
        CPA16(st + (mat * A_U32H + r * RSTR + q * 4) * 4, (const void*)s);
    }
#pragma unroll
    for (int i = 0; i < 3; i++) {             /* B: 1536 CPA16 */
        int gidx = i * 512 + tid;
        int m_ = gidx >> 8, idx = gidx & 255, row = idx >> 2, c = idx & 3;
        const char* src = (const char*)&g_wswg[(size_t)((m_ * 8 + jb) * 16 + kc) * B_GU32];
        CPA16(st + (GRU_BOFFH + m_ * B_U32H + row * RSTR + c * 4) * 4, src + idx * 16);
    }
    CPA_COMMIT();
}

__global__ __launch_bounds__(512, 1) void k_gru_mma(
    const float* __restrict__ emb,
    const float* __restrict__ bir, const float* __restrict__ biz,
    const float* __restrict__ bin, const float* __restrict__ bhn,
    float* __restrict__ out)
{
    extern __shared__ unsigned smu[];
    float* bias_s = (float*)smu;                 /* 256 floats */
    int*   s_tick = (int*)(smu + 256);
    unsigned* stage0 = smu + GRU_HDR_U32;
    uint32_t st0 = smem_u32(stage0);

    int tid = threadIdx.x, lane = tid & 31, warp = tid >> 5;
    int gid = lane >> 2, tig = lane & 3;
    int wm = (warp >> 2) * 32, wn = (warp & 3) * 16;

    for (;;) {
        if (tid == 0) *s_tick = atomicAdd(&g_gtick, 1);
        __syncthreads();
        int t = *s_tick;
        if (t >= NTILE) return;
        int jb = t & 7, m0 = (t >> 3) * 128;

        if (tid < 256) {
            const float* ba[4] = {bir, biz, bin, bhn};
            bias_s[tid] = ba[tid >> 6][jb * 64 + (tid & 63)];
        }

        float accR[2][2][4], accZ[2][2][4], accN[2][2][4], accH[2][2][4];
#pragma unroll
        for (int mf = 0; mf < 2; mf++)
#pragma unroll
            for (int ni = 0; ni < 2; ni++)
#pragma unroll
                for (int q = 0; q < 4; q++) {
                    accR[mf][ni][q] = 0.f; accZ[mf][ni][q] = 0.f;
                    accN[mf][ni][q] = 0.f; accH[mf][ni][q] = 0.f;
                }

        gru_fill(st0, m0, jb, 0, tid);
        gru_fill(st0 + GRU_STAGE_U32 * 4, m0, jb, 1, tid);

        for (int c = 0; c < 16; c++) {
            if (c < 15) CPA_WAIT1(); else CPA_WAIT0();
            __syncthreads();
            if (c + 2 < 16)
                gru_fill(st0 + ((c + 2) % 3) * GRU_STAGE_U32 * 4, m0, jb, c + 2, tid);

            const unsigned* cur = stage0 + (c % 3) * GRU_STAGE_U32;
            const unsigned* Ap = cur;
            const unsigned* Ah = cur + A_U32H;
            const unsigned* Bb = cur + GRU_BOFFH;
#pragma unroll
            for (int ks = 0; ks < 2; ks++) {
                int ko = ks * 8 + tig * 2;
                unsigned ap[2][4], ah[2][4];
#pragma unroll
                for (int mf = 0; mf < 2; mf++) {
                    int r0 = wm + mf * 16 + gid;
                    uint2 v0 = *(const uint2*)(Ap + r0 * RSTR + ko);
                    uint2 v1 = *(const uint2*)(Ap + (r0 + 8) * RSTR + ko);
                    ap[mf][0] = v0.x; ap[mf][1] = v1.x; ap[mf][2] = v0.y; ap[mf][3] = v1.y;
                    uint2 w0 = *(const uint2*)(Ah + r0 * RSTR + ko);
                    uint2 w1 = *(const uint2*)(Ah + (r0 + 8) * RSTR + ko);
                    ah[mf][0] = w0.x; ah[mf][1] = w1.x; ah[mf][2] = w0.y; ah[mf][3] = w1.y;
                }
#pragma unroll
                for (int ni = 0; ni < 2; ni++) {
                    int cb = (wn + ni * 8 + gid) * RSTR + ko;
                    uint2 b;
                    b = *(const uint2*)(Bb + 0 * B_U32H + cb);   /* Wir */
#pragma unroll
                    for (int mf = 0; mf < 2; mf++) mma16(accR[mf][ni], ap[mf], b);
                    b = *(const uint2*)(Bb + 1 * B_U32H + cb);   /* Whr */
#pragma unroll
                    for (int mf = 0; mf < 2; mf++) mma16(accR[mf][ni], ah[mf], b);
                    b = *(const uint2*)(Bb + 2 * B_U32H + cb);   /* Wiz */
#pragma unroll
                    for (int mf = 0; mf < 2; mf++) mma16(accZ[mf][ni], ap[mf], b);
                    b = *(const uint2*)(Bb + 3 * B_U32H + cb);   /* Whz */
#pragma unroll
                    for (int mf = 0; mf < 2; mf++) mma16(accZ[mf][ni], ah[mf], b);
                    b = *(const uint2*)(Bb + 4 * B_U32H + cb);   /* Win */
#pragma unroll
                    for (int mf = 0; mf < 2; mf++) mma16(accN[mf][ni], ap[mf], b);
                    b = *(const uint2*)(Bb + 5 * B_U32H + cb);   /* Whn */
#pragma unroll
                    for (int mf = 0; mf < 2; mf++) mma16(accH[mf][ni], ah[mf], b);
                }
            }
        }

        /* epilogue: gates (h read in fp32) */
#pragma unroll
        for (int mf = 0; mf < 2; mf++) {
#pragma unroll
            for (int rp = 0; rp < 2; rp++) {
                int row = m0 + wm + mf * 16 + rp * 8 + gid;
                if (row >= NN) continue;
                const float* hrow = emb + (size_t)row * HH + jb * 64;
                float* orow = out + (size_t)row * HH + jb * 64;
#pragma unroll
                for (int ni = 0; ni < 2; ni++) {
                    int c0 = wn + ni * 8 + tig * 2;
                    float2 h2 = *(const float2*)(hrow + c0);
                    float o[2];
#pragma unroll
                    for (int e = 0; e < 2; e++) {
                        int q = rp * 2 + e;
                        int cl = c0 + e;
                        float r = sigmoidf_(accR[mf][ni][q] + bias_s[cl]);
                        float z = sigmoidf_(accZ[mf][ni][q] + bias_s[64 + cl]);
                        float n = tanhf(accN[mf][ni][q] + bias_s[128 + cl]
                                        + r * (accH[mf][ni][q] + bias_s[192 + cl]));
                        float h = e ? h2.y : h2.x;
                        o[e] = (1.f - z) * n + z * h;
                    }
                    *(float2*)(orow + c0) = make_float2(o[0], o[1]);
                }
            }
        }
        __syncthreads();     /* protect bias_s / stages before next tile */
    }
}

/* ---------------- edge mma kernel ------------------------------------------
 * 256 threads, 8 warps, warp tile 64x32, CTA tile 256x64. 3-stage pipe,
 * 2 CTAs/SM. fp16x2 REDs directly into interleaved g_prop16.                */
__device__ __forceinline__ void edge_fill(uint32_t st, const int* __restrict__ ssrc,
                                          int jbg, int kc, int tid)
{
#pragma unroll
    for (int i = 0; i < 4; i++) {             /* A: 1024 CPA16 */
        int idx = i * 256 + tid, r = idx >> 2, q = idx & 3;
        int nr = ssrc[r]; if (nr < 0) nr = 0;
        const unsigned* s = g_emb16 + (size_t)nr * 256 + kc * 16 + q * 4;
        CPA16(st + (r * RSTR + q * 4) * 4, (const void*)s);
    }
    {                                          /* B: 256 CPA16 */
        int row = tid >> 2, c = tid & 3;
        const char* src = (const char*)&g_wswe[(size_t)(jbg * 16 + kc) * B_GU32];
        CPA16(st + (EDGE_A_U32 + row * RSTR + c * 4) * 4, src + tid * 16);
    }
    CPA_COMMIT();
}

__global__ __launch_bounds__(256, 2) void k_edge_mma(
    const int* __restrict__ src, const int* __restrict__ dst,
    const float* __restrict__ b_edge)
{
    int start = blockIdx.y * 256;
    if (start >= g_toff[TT]) return;
    int t = 0;
#pragma unroll
    for (int i = 1; i < TT; i++) if (start >= g_toff[i]) t = i;
    int jb8 = blockIdx.x;
    int jbg = t * 8 + jb8;

    extern __shared__ unsigned smu[];
    int* s_srow = (int*)smu;             /* 256 */
    int* s_dst  = (int*)smu + 256;       /* 256 */
    float* s_bias = (float*)smu + 512;   /* 64  */
    unsigned* stage0 = smu + EDGE_HDR_U32;
    uint32_t st0 = smem_u32(stage0);

    int tid = threadIdx.x, lane = tid & 31, warp = tid >> 5;
    int gid = lane >> 2, tig = lane & 3;
    int wm = (warp >> 1) * 64, wn = (warp & 1) * 32;

    {
        int e = g_sorted[start + tid];
        s_srow[tid] = (e >= 0) ? src[e] : -1;
        s_dst[tid]  = (e >= 0) ? dst[e] : -1;
    }
    if (tid < 64) s_bias[tid] = b_edge[(size_t)t * HH + jb8 * 64 + tid];
    __syncthreads();

    float acc[4][4][4];
#pragma unroll
    for (int mf = 0; mf < 4; mf++)
#pragma unroll
        for (int ni = 0; ni < 4; ni++)
#pragma unroll
            for (int q = 0; q < 4; q++) acc[mf][ni][q] = 0.f;

    edge_fill(st0, s_srow, jbg, 0, tid);
    edge_fill(st0 + EDGE_STAGE_U32 * 4, s_srow, jbg, 1, tid);

    for (int c = 0; c < 16; c++) {
        if (c < 15) CPA_WAIT1(); else CPA_WAIT0();
        __syncthreads();
        if (c + 2 < 16)
            edge_fill(st0 + ((c + 2) % 3) * EDGE_STAGE_U32 * 4, s_srow, jbg, c + 2, tid);

        const unsigned* cur = stage0 + (c % 3) * EDGE_STAGE_U32;
        const unsigned* Ap = cur;
        const unsigned* Bb = cur + EDGE_A_U32;
#pragma unroll
        for (int ks = 0; ks < 2; ks++) {
            int ko = ks * 8 + tig * 2;
            unsigned ap[4][4];
#pragma unroll
            for (int mf = 0; mf < 4; mf++) {
                int r0 = wm + mf * 16 + gid;
                uint2 v0 = *(const uint2*)(Ap + r0 * RSTR + ko);
                uint2 v1 = *(const uint2*)(Ap + (r0 + 8) * RSTR + ko);
                ap[mf][0] = v0.x; ap[mf][1] = v1.x; ap[mf][2] = v0.y; ap[mf][3] = v1.y;
            }
#pragma unroll
            for (int ni = 0; ni < 4; ni++) {
                uint2 b = *(const uint2*)(Bb + (wn + ni * 8 + gid) * RSTR + ko);
#pragma unroll
                for (int mf = 0; mf < 4; mf++) mma16(acc[mf][ni], ap[mf], b);
            }
        }
    }

    /* epilogue: bias + fp16x2 scatter reduction into interleaved g_prop16 */
#pragma unroll
    for (int mf = 0; mf < 4; mf++) {
#pragma unroll
        for (int rp = 0; rp < 2; rp++) {
            int arow = wm + mf * 16 + rp * 8 + gid;
            int d = s_dst[arow];
            if (d < 0) continue;
            unsigned* prow = g_prop16 + (size_t)d * 256;
#pragma unroll
            for (int ni = 0; ni < 4; ni++) {
                int cl = wn + ni * 8 + tig * 2;          /* local col (even) */
                int c0 = jb8 * 64 + cl;                  /* global col       */
                int pg = (c0 >> 1) & 7;                  /* pair in 16-group */
                int u32idx = (c0 >> 4) * 8 + 2 * (pg & 3) + (pg >> 2);
                unsigned v = pk2h(acc[mf][ni][rp * 2]     + s_bias[cl],
                                  acc[mf][ni][rp * 2 + 1] + s_bias[cl + 1]);
                redh2(prow + u32idx, v);
            }
        }
    }
}

/* ---------------- launch --------------------------------------------------- */
extern "C" void kernel_launch(void* const* d_in, const int* in_sizes, int n_in,
                              void* d_out, int out_size)
{
    int s = (n_in >= 18) ? 2 : 0;

    const float* emb    = (const float*)d_in[0];
    const int*   src    = (const int*)d_in[1];
    const int*   dst    = (const int*)d_in[2];
    const int*   et     = (const int*)d_in[3];
    const float* W_edge = (const float*)d_in[4 + s];
    const float* b_edge = (const float*)d_in[5 + s];
    const float* Wir    = (const float*)d_in[6 + s];
    const float* Wiz    = (const float*)d_in[7 + s];
    const float* Win    = (const float*)d_in[8 + s];
    const float* bir    = (const float*)d_in[9 + s];
    const float* biz    = (const float*)d_in[10 + s];
    const float* bin    = (const float*)d_in[11 + s];
    const float* Whr    = (const float*)d_in[12 + s];
    const float* Whz    = (const float*)d_in[13 + s];
    const float* Whn    = (const float*)d_in[14 + s];
    const float* bhn    = (const float*)d_in[15 + s];
    float* out = (float*)d_out;

    unsigned* d_e16;  cudaGetSymbolAddress((void**)&d_e16, g_emb16);

    static int attr_done = 0;
    if (!attr_done) {
        cudaFuncSetAttribute(k_gru_mma,  cudaFuncAttributeMaxDynamicSharedMemorySize, GRU_SMEMH);
        cudaFuncSetAttribute(k_edge_mma, cudaFuncAttributeMaxDynamicSharedMemorySize, EDGE_SMEMH);
        attr_done = 1;
    }

    k_init<<<(NN * 64 + 255) / 256, 256>>>();
    k_hist<<<(EE + 255) / 256, 256>>>(et);
    k_scatter<<<(EE + 255) / 256, 256>>>(et);

    k_prep_edge<<<dim3(16, 48), 256>>>(W_edge);
    k_cvt16<<<(NN * 32 + 255) / 256, 256>>>(emb, d_e16);
    k_prep_gru<<<dim3(16, 8, 6), 256>>>(Wir, Whr, Wiz, Whz, Win, Whn);

    k_edge_mma<<<dim3(8, EGRP), 256, EDGE_SMEMH>>>(src, dst, b_edge);

    k_gru_mma<<<160, 512, GRU_SMEMH>>>(emb, bir, biz, bin, bhn, out);
}